// round 15
// baseline (speedup 1.0000x reference)
#include <cuda_runtime.h>
#include <cuda_bf16.h>
#include <cuda_fp16.h>
#include <math.h>
#include <stdint.h>

#define BB 8
#define TT 4096
#define DD 512
#define HH 8
#define HD 64
#define TP 4224
#define NLOC 32
#define NDIL 64

// ---------------- scratch ----------------
__device__ float g_x  [BB*TT*DD];
__device__ __half g_q  [BB*TT*DD];
__device__ __half g_kp [BB*TP*DD];   // local K copy A (rope idx = u&127) / global K
__device__ __half g_kp2[BB*TP*DD];   // local K copy B (rope idx = (u&127)+128)
__device__ __half g_vp [BB*TP*DD];
__device__ __half g_xn [BB*TT*DD];
__device__ __half g_att[BB*TT*DD];
__device__ __half g_h1 [BB*TT*1024];
__device__ __half g_h2 [BB*TT*1024];
__device__ __half g_w  [4194304];
__device__ float g_bcat[3072];
__device__ float g_lcos[256*64];
__device__ float g_lsin[256*64];

// ---------------- helpers ----------------
__device__ __forceinline__ uint32_t smem_u32(const void* p) {
    uint32_t a;
    asm("{ .reg .u64 t; cvta.to.shared.u64 t, %1; cvt.u32.u64 %0, t; }" : "=r"(a) : "l"(p));
    return a;
}
__device__ __forceinline__ void ldsm4(uint32_t* r, uint32_t addr) {
    asm volatile("ldmatrix.sync.aligned.m8n8.x4.shared.b16 {%0,%1,%2,%3}, [%4];"
        : "=r"(r[0]), "=r"(r[1]), "=r"(r[2]), "=r"(r[3]) : "r"(addr));
}
__device__ __forceinline__ void ldsm4t(uint32_t* r, uint32_t addr) {
    asm volatile("ldmatrix.sync.aligned.m8n8.x4.trans.shared.b16 {%0,%1,%2,%3}, [%4];"
        : "=r"(r[0]), "=r"(r[1]), "=r"(r[2]), "=r"(r[3]) : "r"(addr));
}
__device__ __forceinline__ void mma_f16(float* c, const uint32_t* a, uint32_t b0, uint32_t b1) {
    asm volatile("mma.sync.aligned.m16n8k16.row.col.f32.f16.f16.f32 "
        "{%0,%1,%2,%3}, {%4,%5,%6,%7}, {%8,%9}, {%0,%1,%2,%3};"
        : "+f"(c[0]), "+f"(c[1]), "+f"(c[2]), "+f"(c[3])
        : "r"(a[0]), "r"(a[1]), "r"(a[2]), "r"(a[3]), "r"(b0), "r"(b1));
}
#define SWZ64(x) ((x) ^ (((x) >> 3) & 0x30))
#define CPA(dst, src) asm volatile("cp.async.cg.shared.global [%0], [%1], 16;" :: "r"(dst), "l"(src))
#define CPC() asm volatile("cp.async.commit_group;" ::: "memory")
#define CPW(n) asm volatile("cp.async.wait_group %0;" :: "n"(n) : "memory")

__device__ __forceinline__ uint32_t packh(float a, float b) {
    __half2 h = __floats2half2_rn(a, b);
    return *(uint32_t*)&h;
}
__device__ __forceinline__ uint2 pack4h(float4 v) {
    uint2 r; r.x = packh(v.x, v.y); r.y = packh(v.z, v.w); return r;
}

// ---------------- GEMM (fp16): CTA 128x256, warp tile 32x64, BK=64, 3-stage ----------------
// modes: 1=fp16 out, 2=QKV triple (fp16, rope in epilogue), 3=fp32+residual+mask
#define GSTG 49152
__global__ void __launch_bounds__(512, 1) gemm_mma_kernel(
    const __half* __restrict__ A, const __half* __restrict__ W,
    const float* __restrict__ bias,
    float* __restrict__ Cf, __half* __restrict__ Ch,
    __half* __restrict__ Ck, __half* __restrict__ Ck2, __half* __restrict__ Cv,
    const float* __restrict__ R, const int* __restrict__ pm,
    const float* __restrict__ cosg, const float* __restrict__ sing,
    int K, int Nt, int act, int mode, int padKV, int ropeMode)
{
    extern __shared__ char sm[];
    uint32_t smb = smem_u32(sm);
    int tid = threadIdx.x, lane = tid & 31, wid = tid >> 5;
    int row0 = blockIdx.y * 128, col0 = blockIdx.x * 256;
    int wm = (wid & 3) * 32, wn = (wid >> 2) * 64;

    float acc[2][8][4];
    #pragma unroll
    for (int i = 0; i < 2; i++)
        #pragma unroll
        for (int j = 0; j < 8; j++)
            #pragma unroll
            for (int c = 0; c < 4; c++) acc[i][j][c] = 0.0f;

    int srow = tid >> 2, sc = tid & 3;
    uint32_t sdA  = SWZ64((uint32_t)(srow * 64 + sc * 16));
    uint32_t sdW0 = sdA;
    uint32_t sdW1 = SWZ64((uint32_t)((128 + srow) * 64 + sc * 16));
    size_t gA  = (size_t)(row0 + srow) * K + sc * 8;
    size_t gW0 = (size_t)(col0 + srow) * K + sc * 8;
    size_t gW1 = (size_t)(col0 + 128 + srow) * K + sc * 8;

    uint32_t aoff[2], boff[4];
    #pragma unroll
    for (int i = 0; i < 2; i++) {
        int r = wm + i * 16 + (lane & 15);
        aoff[i] = r * 64 + ((lane >> 4) << 4);
    }
    #pragma unroll
    for (int j = 0; j < 4; j++) {
        int r = wn + j * 16 + (lane & 7) + ((lane >> 4) & 1) * 8;
        boff[j] = r * 64 + (((lane >> 3) & 1) << 4);
    }

    int nch = K >> 6;
    #define G_ISSUE(ch) { \
        uint32_t st_ = smb + ((ch) % 3) * GSTG; \
        size_t k0_ = (size_t)(ch) * 64; \
        CPA(st_ + sdA,                  A + gA  + k0_); \
        CPA(st_ + 8192 + sdW0,          W + gW0 + k0_); \
        CPA(st_ + 8192 + sdW1,          W + gW1 + k0_); \
        CPA(st_ + 24576 + sdA,          A + gA  + k0_ + 32); \
        CPA(st_ + 24576 + 8192 + sdW0,  W + gW0 + k0_ + 32); \
        CPA(st_ + 24576 + 8192 + sdW1,  W + gW1 + k0_ + 32); \
        CPC(); }

    G_ISSUE(0);
    if (nch > 1) G_ISSUE(1);

    for (int ch = 0; ch < nch; ch++) {
        if (ch + 1 < nch) { CPW(1); } else { CPW(0); }
        __syncthreads();
        if (ch + 2 < nch) G_ISSUE(ch + 2);
        uint32_t st = smb + (ch % 3) * GSTG;
        #pragma unroll
        for (int sub = 0; sub < 2; sub++) {
            uint32_t sA = st + sub * 24576;
            uint32_t sW = sA + 8192;
            #pragma unroll
            for (int ks = 0; ks < 2; ks++) {
                uint32_t ah[2][4], bh[4][4];
                #pragma unroll
                for (int i = 0; i < 2; i++)
                    ldsm4(ah[i], sA + SWZ64(aoff[i] + ks * 32));
                #pragma unroll
                for (int j = 0; j < 4; j++)
                    ldsm4(bh[j], sW + SWZ64(boff[j] + ks * 32));
                #pragma unroll
                for (int i = 0; i < 2; i++)
                    #pragma unroll
                    for (int j = 0; j < 4; j++) {
                        mma_f16(acc[i][2*j],   ah[i], bh[j][0], bh[j][1]);
                        mma_f16(acc[i][2*j+1], ah[i], bh[j][2], bh[j][3]);
                    }
            }
        }
    }

    int g = lane >> 2, t4 = lane & 3;

    if (mode == 2) {
        // QKV epilogue with fused RoPE (pairs nj and nj+4 are d and d+32)
        #pragma unroll
        for (int i = 0; i < 2; i++) {
            int r1 = row0 + wm + i * 16 + g;
            int r2 = r1 + 8;
            int tt1 = r1 & 4095, tt2 = r2 & 4095;
            int bb1 = r1 >> 12,  bb2 = r2 >> 12;
            #pragma unroll
            for (int njp = 0; njp < 4; njp++) {
                int colLo = col0 + wn + njp * 8 + t4 * 2;
                int seg = colLo >> 9;
                int colL = colLo & 511;
                int dd = colL & 63;   // < 32
                float bl0 = bias[colLo], bl1 = bias[colLo + 1];
                float bh0 = bias[colLo + 32], bh1 = bias[colLo + 33];
                float lo0 = acc[i][njp][0] + bl0, lo1 = acc[i][njp][1] + bl1;
                float lo2 = acc[i][njp][2] + bl0, lo3 = acc[i][njp][3] + bl1;
                float hi0 = acc[i][njp+4][0] + bh0, hi1 = acc[i][njp+4][1] + bh1;
                float hi2 = acc[i][njp+4][2] + bh0, hi3 = acc[i][njp+4][3] + bh1;
                if (seg == 2) {
                    size_t o1 = padKV ? ((size_t)bb1 * TP + 64 + tt1) : (size_t)r1;
                    size_t o2 = padKV ? ((size_t)bb2 * TP + 64 + tt2) : (size_t)r2;
                    *(uint32_t*)(Cv + o1 * 512 + colL)      = packh(lo0, lo1);
                    *(uint32_t*)(Cv + o1 * 512 + colL + 32) = packh(hi0, hi1);
                    *(uint32_t*)(Cv + o2 * 512 + colL)      = packh(lo2, lo3);
                    *(uint32_t*)(Cv + o2 * 512 + colL + 32) = packh(hi2, hi3);
                } else if (ropeMode == 2) {
                    float c10 = cosg[tt1*64+dd], c11 = cosg[tt1*64+dd+1];
                    float s10 = sing[tt1*64+dd], s11 = sing[tt1*64+dd+1];
                    float c20 = cosg[tt2*64+dd], c21 = cosg[tt2*64+dd+1];
                    float s20 = sing[tt2*64+dd], s21 = sing[tt2*64+dd+1];
                    __half* dst = (seg == 0) ? Ch : Ck;
                    *(uint32_t*)(dst + (size_t)r1 * 512 + colL)      = packh(lo0*c10 - hi0*s10, lo1*c11 - hi1*s11);
                    *(uint32_t*)(dst + (size_t)r1 * 512 + colL + 32) = packh(hi0*c10 + lo0*s10, hi1*c11 + lo1*s11);
                    *(uint32_t*)(dst + (size_t)r2 * 512 + colL)      = packh(lo2*c20 - hi2*s20, lo3*c21 - hi3*s21);
                    *(uint32_t*)(dst + (size_t)r2 * 512 + colL + 32) = packh(hi2*c20 + lo2*s20, hi3*c21 + lo3*s21);
                } else if (seg == 0) {
                    // local q: rope idx = 64 + (t & 127)
                    int i1 = 64 + (tt1 & 127), i2 = 64 + (tt2 & 127);
                    float c10 = g_lcos[i1*64+dd], c11 = g_lcos[i1*64+dd+1];
                    float s10 = g_lsin[i1*64+dd], s11 = g_lsin[i1*64+dd+1];
                    float c20 = g_lcos[i2*64+dd], c21 = g_lcos[i2*64+dd+1];
                    float s20 = g_lsin[i2*64+dd], s21 = g_lsin[i2*64+dd+1];
                    *(uint32_t*)(Ch + (size_t)r1 * 512 + colL)      = packh(lo0*c10 - hi0*s10, lo1*c11 - hi1*s11);
                    *(uint32_t*)(Ch + (size_t)r1 * 512 + colL + 32) = packh(hi0*c10 + lo0*s10, hi1*c11 + lo1*s11);
                    *(uint32_t*)(Ch + (size_t)r2 * 512 + colL)      = packh(lo2*c20 - hi2*s20, lo3*c21 - hi3*s21);
                    *(uint32_t*)(Ch + (size_t)r2 * 512 + colL + 32) = packh(hi2*c20 + lo2*s20, hi3*c21 + lo3*s21);
                } else {
                    // local k: two pre-rotated copies in padded layout
                    int u1 = tt1 + 64, u2 = tt2 + 64;
                    int a1 = u1 & 127, a2 = u2 & 127;
                    size_t o1 = (size_t)bb1 * TP + u1;
                    size_t o2 = (size_t)bb2 * TP + u2;
                    float cA10 = g_lcos[a1*64+dd], cA11 = g_lcos[a1*64+dd+1];
                    float sA10 = g_lsin[a1*64+dd], sA11 = g_lsin[a1*64+dd+1];
                    float cA20 = g_lcos[a2*64+dd], cA21 = g_lcos[a2*64+dd+1];
                    float sA20 = g_lsin[a2*64+dd], sA21 = g_lsin[a2*64+dd+1];
                    *(uint32_t*)(Ck + o1 * 512 + colL)      = packh(lo0*cA10 - hi0*sA10, lo1*cA11 - hi1*sA11);
                    *(uint32_t*)(Ck + o1 * 512 + colL + 32) = packh(hi0*cA10 + lo0*sA10, hi1*cA11 + lo1*sA11);
                    *(uint32_t*)(Ck + o2 * 512 + colL)      = packh(lo2*cA20 - hi2*sA20, lo3*cA21 - hi3*sA21);
                    *(uint32_t*)(Ck + o2 * 512 + colL + 32) = packh(hi2*cA20 + lo2*sA20, hi3*cA21 + lo3*sA21);
                    int b1i = a1 + 128, b2i = a2 + 128;
                    float cB10 = g_lcos[b1i*64+dd], cB11 = g_lcos[b1i*64+dd+1];
                    float sB10 = g_lsin[b1i*64+dd], sB11 = g_lsin[b1i*64+dd+1];
                    float cB20 = g_lcos[b2i*64+dd], cB21 = g_lcos[b2i*64+dd+1];
                    float sB20 = g_lsin[b2i*64+dd], sB21 = g_lsin[b2i*64+dd+1];
                    *(uint32_t*)(Ck2 + o1 * 512 + colL)      = packh(lo0*cB10 - hi0*sB10, lo1*cB11 - hi1*sB11);
                    *(uint32_t*)(Ck2 + o1 * 512 + colL + 32) = packh(hi0*cB10 + lo0*sB10, hi1*cB11 + lo1*sB11);
                    *(uint32_t*)(Ck2 + o2 * 512 + colL)      = packh(lo2*cB20 - hi2*sB20, lo3*cB21 - hi3*sB21);
                    *(uint32_t*)(Ck2 + o2 * 512 + colL + 32) = packh(hi2*cB20 + lo2*sB20, hi3*cB21 + lo3*sB21);
                }
            }
        }
        return;
    }

    #pragma unroll
    for (int i = 0; i < 2; i++) {
        int r1 = row0 + wm + i * 16 + g;
        int r2 = r1 + 8;
        #pragma unroll
        for (int nj = 0; nj < 8; nj++) {
            int colG = col0 + wn + nj * 8 + t4 * 2;
            float b0 = bias[colG], b1 = bias[colG + 1];
            float v0 = acc[i][nj][0] + b0, v1 = acc[i][nj][1] + b1;
            float v2 = acc[i][nj][2] + b0, v3 = acc[i][nj][3] + b1;
            if (act) {
                v0 = 0.5f * v0 * (1.0f + erff(v0 * 0.70710678118654752f));
                v1 = 0.5f * v1 * (1.0f + erff(v1 * 0.70710678118654752f));
                v2 = 0.5f * v2 * (1.0f + erff(v2 * 0.70710678118654752f));
                v3 = 0.5f * v3 * (1.0f + erff(v3 * 0.70710678118654752f));
            }
            if (mode == 1) {
                *(uint32_t*)(Ch + (size_t)r1 * Nt + colG) = packh(v0, v1);
                *(uint32_t*)(Ch + (size_t)r2 * Nt + colG) = packh(v2, v3);
            } else {
                float m1 = pm[r1] ? 1.0f : 0.0f;
                float m2 = pm[r2] ? 1.0f : 0.0f;
                const float* rr1 = R + (size_t)r1 * Nt + colG;
                const float* rr2 = R + (size_t)r2 * Nt + colG;
                float2 w1; w1.x = (v0 + rr1[0]) * m1; w1.y = (v1 + rr1[1]) * m1;
                float2 w2; w2.x = (v2 + rr2[0]) * m2; w2.y = (v3 + rr2[1]) * m2;
                *(float2*)(Cf + (size_t)r1 * Nt + colG) = w1;
                *(float2*)(Cf + (size_t)r2 * Nt + colG) = w2;
            }
        }
    }
}

// ---------------- weight convert ----------------
struct WPtrs { const float* p[11]; };
__global__ void cvt_w_kernel(WPtrs wp) {
    const int sizes[11] = {262144,262144,262144,262144,262144,262144,262144,262144,
                           524288,1048576,524288};
    const int offs[11]  = {0,262144,524288, 786432,1048576,1310720,
                           1572864,1835008, 2097152,2621440,3670016};
    int wi = blockIdx.y;
    int i4 = blockIdx.x * blockDim.x + threadIdx.x;
    if (i4 >= (sizes[wi] >> 2)) return;
    float4 v = ((const float4*)wp.p[wi])[i4];
    ((uint2*)(g_w + offs[wi]))[i4] = pack4h(v);
}

struct BPtrs { const float* p[6]; };
__global__ void bias_cat_kernel(BPtrs bp) {
    int t = threadIdx.x;
    for (int i = 0; i < 6; i++)
        g_bcat[i * 512 + t] = bp.p[i][t];
}

// ---------------- local rope tables ----------------
__global__ void rope_init_kernel() {
    int idx = blockIdx.x * blockDim.x + threadIdx.x;
    if (idx >= 256 * 64) return;
    int t = idx >> 6, d = idx & 63;
    double inv = pow(10000.0, -(double)(d & 31) / 32.0);
    double a = (double)t * inv;
    g_lcos[idx] = (float)cos(a);
    g_lsin[idx] = (float)sin(a);
}

// ---------------- layernorm -> fp16 (optional fused input mask + residual copy) ----------------
__global__ void __launch_bounds__(128) ln_kernel(
    const float* __restrict__ X, const float* __restrict__ g,
    const float* __restrict__ b, const int* __restrict__ pm,
    __half* __restrict__ Yh, float* __restrict__ Xout,
    int maskIn, int maskOut)
{
    int row = blockIdx.x;
    int tid = threadIdx.x;
    float4 v = ((const float4*)(X + (size_t)row * DD))[tid];
    float mrow = pm[row] ? 1.0f : 0.0f;
    if (maskIn) {
        v.x *= mrow; v.y *= mrow; v.z *= mrow; v.w *= mrow;
        ((float4*)(Xout + (size_t)row * DD))[tid] = v;
    }
    float s  = v.x + v.y + v.z + v.w;
    float ss = v.x*v.x + v.y*v.y + v.z*v.z + v.w*v.w;
    #pragma unroll
    for (int o = 16; o; o >>= 1) {
        s  += __shfl_xor_sync(~0u, s,  o);
        ss += __shfl_xor_sync(~0u, ss, o);
    }
    __shared__ float sh[8];
    int w = tid >> 5, lane = tid & 31;
    if (lane == 0) { sh[w] = s; sh[4 + w] = ss; }
    __syncthreads();
    s  = sh[0] + sh[1] + sh[2] + sh[3];
    ss = sh[4] + sh[5] + sh[6] + sh[7];
    float mean = s * (1.0f / 512.0f);
    float var  = ss * (1.0f / 512.0f) - mean * mean;
    float inv  = rsqrtf(var + 1e-5f);
    float m = maskOut ? mrow : 1.0f;
    float4 gg = ((const float4*)g)[tid];
    float4 bb = ((const float4*)b)[tid];
    float4 o;
    o.x = ((v.x - mean) * inv * gg.x + bb.x) * m;
    o.y = ((v.y - mean) * inv * gg.y + bb.y) * m;
    o.z = ((v.z - mean) * inv * gg.z + bb.z) * m;
    o.w = ((v.w - mean) * inv * gg.w + bb.w) * m;
    ((uint2*)(Yh + (size_t)row * DD))[tid] = pack4h(o);
}

// ---------------- fill pad rows (rotated bias into both K copies, plain bias into V) ----------------
__global__ void fill_pad_kernel(const float* __restrict__ kb, const float* __restrict__ vb) {
    int idx = blockIdx.x * blockDim.x + threadIdx.x;
    if (idx >= BB * 128 * DD) return;
    int c  = idx & 511;
    int rr = (idx >> 9) & 127;
    int b  = idx >> 16;
    int u = (rr < 64) ? rr : (TT + rr);
    size_t o = ((size_t)b * TP + u) * DD + c;
    int s = u & 127;
    int dd = c & 63;
    float cA = g_lcos[s*64+dd], snA = g_lsin[s*64+dd];
    float cB = g_lcos[(s+128)*64+dd], snB = g_lsin[(s+128)*64+dd];
    float v0 = kb[c];
    float vp = (dd < 32) ? kb[c + 32] : kb[c - 32];
    float sg = (dd < 32) ? -1.0f : 1.0f;
    g_kp [o] = __float2half(v0 * cA + sg * vp * snA);
    g_kp2[o] = __float2half(v0 * cB + sg * vp * snB);
    g_vp [o] = __float2half(vb[c]);
}

// ---------------- local attention (mma, cp.async staging, online softmax over 4 chunks) ----------------
#define ATS 72
__global__ void __launch_bounds__(256, 1) local_attn_kernel(
    const __half* __restrict__ Qg, const int* __restrict__ pm,
    __half* __restrict__ Og)
{
    int j = blockIdx.x, h = blockIdx.y, b = blockIdx.z;
    extern __shared__ char smc[];
    __half* Ks = (__half*)smc;                 // 256 x 72
    __half* Vs = Ks + 256 * ATS;               // 256 x 72
    __half* Qs = Vs + 256 * ATS;               // 128 x 72
    float* keepneg = (float*)(Qs + 128 * ATS); // 256
    int tid = threadIdx.x, lane = tid & 31;

    uint32_t sK = smem_u32(Ks), sV = smem_u32(Vs), sQ = smem_u32(Qs);
    int u0 = j * 128;
    size_t rowB = (size_t)b * TP;
    // K (two pre-rotated copies) + V : pure cp.async
    #pragma unroll
    for (int it = 0; it < 8; it++) {
        int idx = tid + it * 256;
        int r = idx >> 3, k8 = (idx & 7) << 3;
        size_t src = (rowB + u0 + r) * DD + h * HD + k8;
        const __half* kp = (r < 128) ? (g_kp + src) : (g_kp2 + src);
        CPA(sK + (uint32_t)(r * ATS + k8) * 2, kp);
        CPA(sV + (uint32_t)(r * ATS + k8) * 2, g_vp + src);
    }
    // Q (pre-rotated)
    #pragma unroll
    for (int it = 0; it < 4; it++) {
        int idx = tid + it * 256;
        int r = idx >> 3, k8 = (idx & 7) << 3;
        CPA(sQ + (uint32_t)(r * ATS + k8) * 2,
            Qg + ((size_t)b * TT + (size_t)j * 128 + r) * DD + h * HD + k8);
    }
    CPC();
    if (tid < 256) {
        int orig = j * 128 + tid - 64;
        keepneg[tid] = (orig >= 0 && orig < TT && pm[(size_t)b * TT + orig]) ? 0.0f : -1e9f;
    }
    CPW(0);
    __syncthreads();
    if (tid == 0) {
        int any = 0;
        for (int i = 0; i < 256; i++) any |= (keepneg[i] == 0.0f);
        if (!any) keepneg[0] = 0.0f;
    }
    __syncthreads();

    int m0 = (tid >> 5) * 16;
    float O[8][4];
    #pragma unroll
    for (int n = 0; n < 8; n++)
        #pragma unroll
        for (int c = 0; c < 4; c++) O[n][c] = 0.0f;
    float mr_lo = -1e30f, mr_hi = -1e30f, sr_lo = 0.0f, sr_hi = 0.0f;

    uint32_t qbase = sQ + (uint32_t)(((m0 + (lane & 15)) * ATS + ((lane >> 4) << 3)) * 2);
    uint32_t krow = (lane & 7) + ((lane >> 4) & 1) * 8;
    uint32_t kcol = ((lane >> 3) & 1) * 8;
    uint32_t vrow = (lane & 15);
    uint32_t vcol = (lane >> 4) * 8;

    for (int ck = 0; ck < 4; ck++) {
        int k0 = ck * 64;
        float S[8][4];
        #pragma unroll
        for (int n = 0; n < 8; n++)
            #pragma unroll
            for (int c = 0; c < 4; c++) S[n][c] = 0.0f;
        #pragma unroll
        for (int kt = 0; kt < 4; kt++) {
            uint32_t aq[4];
            ldsm4(aq, qbase + kt * 32);
            #pragma unroll
            for (int ntp = 0; ntp < 4; ntp++) {
                uint32_t bk[4];
                ldsm4(bk, sK + (uint32_t)(((k0 + ntp * 16 + krow) * ATS + kt * 16 + kcol) * 2));
                mma_f16(S[2*ntp],   aq, bk[0], bk[1]);
                mma_f16(S[2*ntp+1], aq, bk[2], bk[3]);
            }
        }
        float cm_lo = -1e30f, cm_hi = -1e30f;
        #pragma unroll
        for (int nt = 0; nt < 8; nt++) {
            int colg = k0 + nt * 8 + (lane & 3) * 2;
            float kn0 = keepneg[colg], kn1 = keepneg[colg + 1];
            S[nt][0] = S[nt][0] * 0.125f + kn0;
            S[nt][1] = S[nt][1] * 0.125f + kn1;
            S[nt][2] = S[nt][2] * 0.125f + kn0;
            S[nt][3] = S[nt][3] * 0.125f + kn1;
            cm_lo = fmaxf(cm_lo, fmaxf(S[nt][0], S[nt][1]));
            cm_hi = fmaxf(cm_hi, fmaxf(S[nt][2], S[nt][3]));
        }
        cm_lo = fmaxf(cm_lo, __shfl_xor_sync(~0u, cm_lo, 1));
        cm_lo = fmaxf(cm_lo, __shfl_xor_sync(~0u, cm_lo, 2));
        cm_hi = fmaxf(cm_hi, __shfl_xor_sync(~0u, cm_hi, 1));
        cm_hi = fmaxf(cm_hi, __shfl_xor_sync(~0u, cm_hi, 2));
        float mn_lo = fmaxf(mr_lo, cm_lo), mn_hi = fmaxf(mr_hi, cm_hi);
        float al_lo = expf(mr_lo - mn_lo), al_hi = expf(mr_hi - mn_hi);
        mr_lo = mn_lo; mr_hi = mn_hi;
        sr_lo *= al_lo; sr_hi *= al_hi;
        #pragma unroll
        for (int n = 0; n < 8; n++) {
            O[n][0] *= al_lo; O[n][1] *= al_lo;
            O[n][2] *= al_hi; O[n][3] *= al_hi;
        }
        uint32_t pa[4][4];
        #pragma unroll
        for (int kt = 0; kt < 4; kt++) {
            int t0 = 2 * kt, t1 = 2 * kt + 1;
            float p00 = expf(S[t0][0] - mn_lo), p01 = expf(S[t0][1] - mn_lo);
            float p02 = expf(S[t0][2] - mn_hi), p03 = expf(S[t0][3] - mn_hi);
            float p10 = expf(S[t1][0] - mn_lo), p11 = expf(S[t1][1] - mn_lo);
            float p12 = expf(S[t1][2] - mn_hi), p13 = expf(S[t1][3] - mn_hi);
            sr_lo += p00 + p01 + p10 + p11;
            sr_hi += p02 + p03 + p12 + p13;
            pa[kt][0] = packh(p00, p01);
            pa[kt][1] = packh(p02, p03);
            pa[kt][2] = packh(p10, p11);
            pa[kt][3] = packh(p12, p13);
        }
        #pragma unroll
        for (int kt = 0; kt < 4; kt++) {
            #pragma unroll
            for (int ntp = 0; ntp < 4; ntp++) {
                uint32_t vf[4];
                ldsm4t(vf, sV + (uint32_t)(((k0 + kt * 16 + vrow) * ATS + ntp * 16 + vcol) * 2));
                mma_f16(O[2*ntp],   pa[kt], vf[0], vf[1]);
                mma_f16(O[2*ntp+1], pa[kt], vf[2], vf[3]);
            }
        }
    }
    sr_lo += __shfl_xor_sync(~0u, sr_lo, 1);
    sr_lo += __shfl_xor_sync(~0u, sr_lo, 2);
    sr_hi += __shfl_xor_sync(~0u, sr_hi, 1);
    sr_hi += __shfl_xor_sync(~0u, sr_hi, 2);
    float inv_lo = 1.0f / sr_lo, inv_hi = 1.0f / sr_hi;

    int r_lo = j * 128 + m0 + (lane >> 2);
    int r_hi = r_lo + 8;
    size_t b_lo = ((size_t)b * TT + r_lo) * DD + h * HD;
    size_t b_hi = ((size_t)b * TT + r_hi) * DD + h * HD;
    #pragma unroll
    for (int nt = 0; nt < 8; nt++) {
        int col = nt * 8 + (lane & 3) * 2;
        *(uint32_t*)&Og[b_lo + col] = packh(O[nt][0] * inv_lo, O[nt][1] * inv_lo);
        *(uint32_t*)&Og[b_hi + col] = packh(O[nt][2] * inv_hi, O[nt][3] * inv_hi);
    }
}

// ---------------- global (dilated) attention (mma, cp.async staging, single 64-key tile) ----------------
__global__ void __launch_bounds__(128, 1) global_attn_kernel(
    const __half* __restrict__ Qg, const __half* __restrict__ Kg,
    const __half* __restrict__ Vg, const int* __restrict__ pm,
    __half* __restrict__ Og)
{
    int w = blockIdx.x, h = blockIdx.y, b = blockIdx.z;
    extern __shared__ char smc[];
    __half* Qs = (__half*)smc;                 // 64 x 72
    __half* Ks = Qs + 64 * ATS;
    __half* Vs = Ks + 64 * ATS;
    float* keepneg = (float*)(Vs + 64 * ATS);  // 64
    int tid = threadIdx.x, lane = tid & 31;

    uint32_t sQ = smem_u32(Qs), sK = smem_u32(Ks), sV = smem_u32(Vs);
    #pragma unroll
    for (int it = 0; it < 4; it++) {
        int idx = tid + it * 128;
        int r = idx >> 3, k8 = (idx & 7) << 3;
        int p = r * 64 + w;
        size_t base = ((size_t)b * TT + p) * DD + h * HD + k8;
        uint32_t doff = (uint32_t)(r * ATS + k8) * 2;
        CPA(sQ + doff, Qg + base);
        CPA(sK + doff, Kg + base);
        CPA(sV + doff, Vg + base);
    }
    CPC();
    if (tid < 64) keepneg[tid] = pm[(size_t)b * TT + tid * 64 + w] ? 0.0f : -1e9f;
    CPW(0);
    __syncthreads();

    int m0 = (tid >> 5) * 16;
    uint32_t qbase = sQ + (uint32_t)(((m0 + (lane & 15)) * ATS + ((lane >> 4) << 3)) * 2);
    uint32_t krow = (lane & 7) + ((lane >> 4) & 1) * 8;
    uint32_t kcol = ((lane >> 3) & 1) * 8;
    uint32_t vrow = (lane & 15);
    uint32_t vcol = (lane >> 4) * 8;

    float S[8][4];
    #pragma unroll
    for (int n = 0; n < 8; n++)
        #pragma unroll
        for (int c = 0; c < 4; c++) S[n][c] = 0.0f;
    #pragma unroll
    for (int kt = 0; kt < 4; kt++) {
        uint32_t aq[4];
        ldsm4(aq, qbase + kt * 32);
        #pragma unroll
        for (int ntp = 0; ntp < 4; ntp++) {
            uint32_t bk[4];
            ldsm4(bk, sK + (uint32_t)(((ntp * 16 + krow) * ATS + kt * 16 + kcol) * 2));
            mma_f16(S[2*ntp],   aq, bk[0], bk[1]);
            mma_f16(S[2*ntp+1], aq, bk[2], bk[3]);
        }
    }
    float cm_lo = -1e30f, cm_hi = -1e30f;
    #pragma unroll
    for (int nt = 0; nt < 8; nt++) {
        int colg = nt * 8 + (lane & 3) * 2;
        float kn0 = keepneg[colg], kn1 = keepneg[colg + 1];
        S[nt][0] = S[nt][0] * 0.125f + kn0;
        S[nt][1] = S[nt][1] * 0.125f + kn1;
        S[nt][2] = S[nt][2] * 0.125f + kn0;
        S[nt][3] = S[nt][3] * 0.125f + kn1;
        cm_lo = fmaxf(cm_lo, fmaxf(S[nt][0], S[nt][1]));
        cm_hi = fmaxf(cm_hi, fmaxf(S[nt][2], S[nt][3]));
    }
    cm_lo = fmaxf(cm_lo, __shfl_xor_sync(~0u, cm_lo, 1));
    cm_lo = fmaxf(cm_lo, __shfl_xor_sync(~0u, cm_lo, 2));
    cm_hi = fmaxf(cm_hi, __shfl_xor_sync(~0u, cm_hi, 1));
    cm_hi = fmaxf(cm_hi, __shfl_xor_sync(~0u, cm_hi, 2));

    float sr_lo = 0.0f, sr_hi = 0.0f;
    uint32_t pa[4][4];
    float O[8][4];
    #pragma unroll
    for (int n = 0; n < 8; n++)
        #pragma unroll
        for (int c = 0; c < 4; c++) O[n][c] = 0.0f;
    #pragma unroll
    for (int kt = 0; kt < 4; kt++) {
        int t0 = 2 * kt, t1 = 2 * kt + 1;
        float p00 = expf(S[t0][0] - cm_lo), p01 = expf(S[t0][1] - cm_lo);
        float p02 = expf(S[t0][2] - cm_hi), p03 = expf(S[t0][3] - cm_hi);
        float p10 = expf(S[t1][0] - cm_lo), p11 = expf(S[t1][1] - cm_lo);
        float p12 = expf(S[t1][2] - cm_hi), p13 = expf(S[t1][3] - cm_hi);
        sr_lo += p00 + p01 + p10 + p11;
        sr_hi += p02 + p03 + p12 + p13;
        pa[kt][0] = packh(p00, p01);
        pa[kt][1] = packh(p02, p03);
        pa[kt][2] = packh(p10, p11);
        pa[kt][3] = packh(p12, p13);
    }
    #pragma unroll
    for (int kt = 0; kt < 4; kt++) {
        #pragma unroll
        for (int ntp = 0; ntp < 4; ntp++) {
            uint32_t vf[4];
            ldsm4t(vf, sV + (uint32_t)(((kt * 16 + vrow) * ATS + ntp * 16 + vcol) * 2));
            mma_f16(O[2*ntp],   pa[kt], vf[0], vf[1]);
            mma_f16(O[2*ntp+1], pa[kt], vf[2], vf[3]);
        }
    }
    sr_lo += __shfl_xor_sync(~0u, sr_lo, 1);
    sr_lo += __shfl_xor_sync(~0u, sr_lo, 2);
    sr_hi += __shfl_xor_sync(~0u, sr_hi, 1);
    sr_hi += __shfl_xor_sync(~0u, sr_hi, 2);
    float inv_lo = 1.0f / sr_lo, inv_hi = 1.0f / sr_hi;

    int p_lo = (m0 + (lane >> 2)) * 64 + w;
    int p_hi = p_lo + 8 * 64;
    size_t b_lo = ((size_t)b * TT + p_lo) * DD + h * HD;
    size_t b_hi = ((size_t)b * TT + p_hi) * DD + h * HD;
    #pragma unroll
    for (int nt = 0; nt < 8; nt++) {
        int col = nt * 8 + (lane & 3) * 2;
        *(uint32_t*)&Og[b_lo + col] = packh(O[nt][0] * inv_lo, O[nt][1] * inv_lo);
        *(uint32_t*)&Og[b_hi + col] = packh(O[nt][2] * inv_hi, O[nt][3] * inv_hi);
    }
}

// ---------------- host ----------------
extern "C" void kernel_launch(void* const* d_in, const int* in_sizes, int n_in,
                              void* d_out, int out_size)
{
    const float* x    = (const float*)d_in[0];
    const int*   pm   = (const int*)d_in[1];
    const float* cosp = (const float*)d_in[2];
    const float* sinp = (const float*)d_in[3];
    const float* ln1_g = (const float*)d_in[4];
    const float* ln1_b = (const float*)d_in[5];
    const float* ln2_g = (const float*)d_in[6];
    const float* ln2_b = (const float*)d_in[7];
    const float* ln3_g = (const float*)d_in[8];
    const float* ln3_b = (const float*)d_in[9];
    const float* lq_w = (const float*)d_in[10];
    const float* lq_b = (const float*)d_in[11];
    const float* lk_w = (const float*)d_in[12];
    const float* lk_b = (const float*)d_in[13];
    const float* lv_w = (const float*)d_in[14];
    const float* lv_b = (const float*)d_in[15];
    const float* lo_w = (const float*)d_in[16];
    const float* lo_b = (const float*)d_in[17];
    const float* gq_w = (const float*)d_in[18];
    const float* gq_b = (const float*)d_in[19];
    const float* gk_w = (const float*)d_in[20];
    const float* gk_b = (const float*)d_in[21];
    const float* gv_w = (const float*)d_in[22];
    const float* gv_b = (const float*)d_in[23];
    const float* go_w = (const float*)d_in[24];
    const float* go_b = (const float*)d_in[25];
    const float* f1_w = (const float*)d_in[26];
    const float* f1_b = (const float*)d_in[27];
    const float* f2_w = (const float*)d_in[28];
    const float* f2_b = (const float*)d_in[29];
    const float* f3_w = (const float*)d_in[30];
    const float* f3_b = (const float*)d_in[31];
    float* out = (float*)d_out;

    float *px, *pbcat;
    __half *pq, *pkp, *pkp2, *pvp, *pxn, *patt, *ph1, *ph2, *pw;
    cudaGetSymbolAddress((void**)&px,    g_x);
    cudaGetSymbolAddress((void**)&pq,    g_q);
    cudaGetSymbolAddress((void**)&pkp,   g_kp);
    cudaGetSymbolAddress((void**)&pkp2,  g_kp2);
    cudaGetSymbolAddress((void**)&pvp,   g_vp);
    cudaGetSymbolAddress((void**)&pbcat, g_bcat);
    cudaGetSymbolAddress((void**)&pxn,   g_xn);
    cudaGetSymbolAddress((void**)&patt,  g_att);
    cudaGetSymbolAddress((void**)&ph1,   g_h1);
    cudaGetSymbolAddress((void**)&ph2,   g_h2);
    cudaGetSymbolAddress((void**)&pw,    g_w);

    const int M = BB * TT;
    const int EW = 256;

    size_t smLoc = (size_t)(2 * 256 * ATS + 128 * ATS) * 2 + 256 * 4;
    size_t smGlb = (size_t)(3 * 64 * ATS) * 2 + 64 * 4;
    size_t smGemm = 3 * GSTG;
    cudaFuncSetAttribute(local_attn_kernel,  cudaFuncAttributeMaxDynamicSharedMemorySize, (int)smLoc);
    cudaFuncSetAttribute(global_attn_kernel, cudaFuncAttributeMaxDynamicSharedMemorySize, (int)smGlb);
    cudaFuncSetAttribute(gemm_mma_kernel, cudaFuncAttributeMaxDynamicSharedMemorySize, (int)smGemm);

    const int OLQKV=0, OGQKV=786432, OLO=1572864, OGO=1835008,
              OF1=2097152, OF2=2621440, OF3=3670016;

    dim3 gQKV(6, M / 128);
    dim3 g512(2, M / 128);
    dim3 g1k (4, M / 128);

    rope_init_kernel<<<64, 256>>>();
    WPtrs wp;
    wp.p[0]=lq_w; wp.p[1]=lk_w; wp.p[2]=lv_w; wp.p[3]=gq_w; wp.p[4]=gk_w;
    wp.p[5]=gv_w; wp.p[6]=lo_w; wp.p[7]=go_w; wp.p[8]=f1_w; wp.p[9]=f2_w; wp.p[10]=f3_w;
    cvt_w_kernel<<<dim3(1024, 11), 256>>>(wp);
    BPtrs bp;
    bp.p[0]=lq_b; bp.p[1]=lk_b; bp.p[2]=lv_b; bp.p[3]=gq_b; bp.p[4]=gk_b; bp.p[5]=gv_b;
    bias_cat_kernel<<<1, 512>>>(bp);

    // fused: px = x*mask; xn = LN(px)*mask
    ln_kernel<<<M, 128>>>(x, ln1_g, ln1_b, pm, pxn, px, 1, 1);

    // local QKV fused, rope in epilogue (q rotated, k two rotated padded copies, v padded)
    gemm_mma_kernel<<<gQKV, 512, smGemm>>>(pxn, pw+OLQKV, pbcat,
                                           0, pq, pkp, pkp2, pvp, 0, 0, 0, 0,
                                           DD, DD, 0, 2, 1, 1);
    fill_pad_kernel<<<(BB * 128 * DD + EW - 1) / EW, EW>>>(lk_b, lv_b);

    local_attn_kernel<<<dim3(NLOC, HH, BB), 256, smLoc>>>(pq, pm, patt);

    // O proj + residual + mask (in place on px)
    gemm_mma_kernel<<<g512, 512, smGemm>>>(patt, pw+OLO, lo_b,
                                           px, 0, 0, 0, 0, px, pm, 0, 0,
                                           DD, DD, 0, 3, 0, 0);

    ln_kernel<<<M, 128>>>(px, ln2_g, ln2_b, pm, pxn, 0, 0, 0);

    // global QKV fused, rope (absolute pos) in epilogue
    gemm_mma_kernel<<<gQKV, 512, smGemm>>>(pxn, pw+OGQKV, pbcat + 1536,
                                           0, pq, pkp, 0, pvp, 0, 0, cosp, sinp,
                                           DD, DD, 0, 2, 0, 2);

    global_attn_kernel<<<dim3(NDIL, HH, BB), 128, smGlb>>>(pq, pkp, pvp, pm, patt);

    gemm_mma_kernel<<<g512, 512, smGemm>>>(patt, pw+OGO, go_b,
                                           px, 0, 0, 0, 0, px, pm, 0, 0,
                                           DD, DD, 0, 3, 0, 0);

    ln_kernel<<<M, 128>>>(px, ln3_g, ln3_b, pm, pxn, 0, 0, 0);
    gemm_mma_kernel<<<g1k,  512, smGemm>>>(pxn, pw+OF1, f1_b,
                                           0, ph1, 0, 0, 0, 0, 0, 0, 0,
                                           512,  1024, 1, 1, 0, 0);
    gemm_mma_kernel<<<g1k,  512, smGemm>>>(ph1, pw+OF2, f2_b,
                                           0, ph2, 0, 0, 0, 0, 0, 0, 0,
                                           1024, 1024, 1, 1, 0, 0);
    // f3 + residual + mask -> out
    gemm_mma_kernel<<<g512, 512, smGemm>>>(ph2, pw+OF3, f3_b,
                                           out, 0, 0, 0, 0, px, pm, 0, 0,
                                           1024, 512, 0, 3, 0, 0);
}

// round 16
// speedup vs baseline: 1.0116x; 1.0116x over previous
#include <cuda_runtime.h>
#include <cuda_bf16.h>
#include <cuda_fp16.h>
#include <math.h>
#include <stdint.h>

#define BB 8
#define TT 4096
#define DD 512
#define HH 8
#define HD 64
#define TP 4224
#define NLOC 32
#define NDIL 64

// ---------------- scratch ----------------
__device__ float g_x  [BB*TT*DD];
__device__ __half g_q  [BB*TT*DD];
__device__ __half g_kp [BB*TP*DD];
__device__ __half g_vp [BB*TP*DD];
__device__ __half g_xn [BB*TT*DD];
__device__ __half g_att[BB*TT*DD];
__device__ __half g_h1 [BB*TT*1024];
__device__ __half g_h2 [BB*TT*1024];
__device__ __half g_w  [4194304];
__device__ float g_bcat[3072];
__device__ float g_lcos[256*64];
__device__ float g_lsin[256*64];

// ---------------- helpers ----------------
__device__ __forceinline__ uint32_t smem_u32(const void* p) {
    uint32_t a;
    asm("{ .reg .u64 t; cvta.to.shared.u64 t, %1; cvt.u32.u64 %0, t; }" : "=r"(a) : "l"(p));
    return a;
}
__device__ __forceinline__ void ldsm4(uint32_t* r, uint32_t addr) {
    asm volatile("ldmatrix.sync.aligned.m8n8.x4.shared.b16 {%0,%1,%2,%3}, [%4];"
        : "=r"(r[0]), "=r"(r[1]), "=r"(r[2]), "=r"(r[3]) : "r"(addr));
}
__device__ __forceinline__ void ldsm4t(uint32_t* r, uint32_t addr) {
    asm volatile("ldmatrix.sync.aligned.m8n8.x4.trans.shared.b16 {%0,%1,%2,%3}, [%4];"
        : "=r"(r[0]), "=r"(r[1]), "=r"(r[2]), "=r"(r[3]) : "r"(addr));
}
__device__ __forceinline__ void mma_f16(float* c, const uint32_t* a, uint32_t b0, uint32_t b1) {
    asm volatile("mma.sync.aligned.m16n8k16.row.col.f32.f16.f16.f32 "
        "{%0,%1,%2,%3}, {%4,%5,%6,%7}, {%8,%9}, {%0,%1,%2,%3};"
        : "+f"(c[0]), "+f"(c[1]), "+f"(c[2]), "+f"(c[3])
        : "r"(a[0]), "r"(a[1]), "r"(a[2]), "r"(a[3]), "r"(b0), "r"(b1));
}
#define SWZ64(x) ((x) ^ (((x) >> 3) & 0x30))
#define CPA(dst, src) asm volatile("cp.async.cg.shared.global [%0], [%1], 16;" :: "r"(dst), "l"(src))
#define CPC() asm volatile("cp.async.commit_group;" ::: "memory")
#define CPW(n) asm volatile("cp.async.wait_group %0;" :: "n"(n) : "memory")

__device__ __forceinline__ uint32_t packh(float a, float b) {
    __half2 h = __floats2half2_rn(a, b);
    return *(uint32_t*)&h;
}
__device__ __forceinline__ uint2 pack4h(float4 v) {
    uint2 r; r.x = packh(v.x, v.y); r.y = packh(v.z, v.w); return r;
}
__device__ __forceinline__ void unpack4h(uint2 u, float* f) {
    __half2 a = *(__half2*)&u.x, b = *(__half2*)&u.y;
    f[0] = __low2float(a); f[1] = __high2float(a);
    f[2] = __low2float(b); f[3] = __high2float(b);
}

// ---------------- GEMM (fp16): CTA 128x256, warp tile 32x64, BK=64, 3-stage ----------------
// modes: 1=fp16 out, 2=QKV triple (fp16), 3=fp32+residual+mask
#define GSTG 49152
__global__ void __launch_bounds__(512, 1) gemm_mma_kernel(
    const __half* __restrict__ A, const __half* __restrict__ W,
    const float* __restrict__ bias,
    float* __restrict__ Cf, __half* __restrict__ Ch,
    __half* __restrict__ Ck, __half* __restrict__ Cv,
    const float* __restrict__ R, const int* __restrict__ pm,
    int K, int Nt, int act, int mode, int padKV)
{
    extern __shared__ char sm[];
    uint32_t smb = smem_u32(sm);
    int tid = threadIdx.x, lane = tid & 31, wid = tid >> 5;
    int row0 = blockIdx.y * 128, col0 = blockIdx.x * 256;
    int wm = (wid & 3) * 32, wn = (wid >> 2) * 64;

    float acc[2][8][4];
    #pragma unroll
    for (int i = 0; i < 2; i++)
        #pragma unroll
        for (int j = 0; j < 8; j++)
            #pragma unroll
            for (int c = 0; c < 4; c++) acc[i][j][c] = 0.0f;

    int srow = tid >> 2, sc = tid & 3;
    uint32_t sdA  = SWZ64((uint32_t)(srow * 64 + sc * 16));
    uint32_t sdW0 = sdA;
    uint32_t sdW1 = SWZ64((uint32_t)((128 + srow) * 64 + sc * 16));
    size_t gA  = (size_t)(row0 + srow) * K + sc * 8;
    size_t gW0 = (size_t)(col0 + srow) * K + sc * 8;
    size_t gW1 = (size_t)(col0 + 128 + srow) * K + sc * 8;

    uint32_t aoff[2], boff[4];
    #pragma unroll
    for (int i = 0; i < 2; i++) {
        int r = wm + i * 16 + (lane & 15);
        aoff[i] = r * 64 + ((lane >> 4) << 4);
    }
    #pragma unroll
    for (int j = 0; j < 4; j++) {
        int r = wn + j * 16 + (lane & 7) + ((lane >> 4) & 1) * 8;
        boff[j] = r * 64 + (((lane >> 3) & 1) << 4);
    }

    int nch = K >> 6;
    #define G_ISSUE(ch) { \
        uint32_t st_ = smb + ((ch) % 3) * GSTG; \
        size_t k0_ = (size_t)(ch) * 64; \
        CPA(st_ + sdA,                  A + gA  + k0_); \
        CPA(st_ + 8192 + sdW0,          W + gW0 + k0_); \
        CPA(st_ + 8192 + sdW1,          W + gW1 + k0_); \
        CPA(st_ + 24576 + sdA,          A + gA  + k0_ + 32); \
        CPA(st_ + 24576 + 8192 + sdW0,  W + gW0 + k0_ + 32); \
        CPA(st_ + 24576 + 8192 + sdW1,  W + gW1 + k0_ + 32); \
        CPC(); }

    G_ISSUE(0);
    if (nch > 1) G_ISSUE(1);

    for (int ch = 0; ch < nch; ch++) {
        if (ch + 1 < nch) { CPW(1); } else { CPW(0); }
        __syncthreads();
        if (ch + 2 < nch) G_ISSUE(ch + 2);
        uint32_t st = smb + (ch % 3) * GSTG;
        #pragma unroll
        for (int sub = 0; sub < 2; sub++) {
            uint32_t sA = st + sub * 24576;
            uint32_t sW = sA + 8192;
            #pragma unroll
            for (int ks = 0; ks < 2; ks++) {
                uint32_t ah[2][4], bh[4][4];
                #pragma unroll
                for (int i = 0; i < 2; i++)
                    ldsm4(ah[i], sA + SWZ64(aoff[i] + ks * 32));
                #pragma unroll
                for (int j = 0; j < 4; j++)
                    ldsm4(bh[j], sW + SWZ64(boff[j] + ks * 32));
                #pragma unroll
                for (int i = 0; i < 2; i++)
                    #pragma unroll
                    for (int j = 0; j < 4; j++) {
                        mma_f16(acc[i][2*j],   ah[i], bh[j][0], bh[j][1]);
                        mma_f16(acc[i][2*j+1], ah[i], bh[j][2], bh[j][3]);
                    }
            }
        }
    }

    // epilogue
    int g = lane >> 2, t4 = lane & 3;
    #pragma unroll
    for (int i = 0; i < 2; i++) {
        int r1 = row0 + wm + i * 16 + g;
        int r2 = r1 + 8;
        #pragma unroll
        for (int nj = 0; nj < 8; nj++) {
            int colG = col0 + wn + nj * 8 + t4 * 2;
            float b0 = bias[colG], b1 = bias[colG + 1];
            float v0 = acc[i][nj][0] + b0, v1 = acc[i][nj][1] + b1;
            float v2 = acc[i][nj][2] + b0, v3 = acc[i][nj][3] + b1;
            if (act) {
                v0 = 0.5f * v0 * (1.0f + erff(v0 * 0.70710678118654752f));
                v1 = 0.5f * v1 * (1.0f + erff(v1 * 0.70710678118654752f));
                v2 = 0.5f * v2 * (1.0f + erff(v2 * 0.70710678118654752f));
                v3 = 0.5f * v3 * (1.0f + erff(v3 * 0.70710678118654752f));
            }
            if (mode == 1) {
                *(uint32_t*)(Ch + (size_t)r1 * Nt + colG) = packh(v0, v1);
                *(uint32_t*)(Ch + (size_t)r2 * Nt + colG) = packh(v2, v3);
            } else if (mode == 2) {
                int seg = colG >> 9;
                int colLoc = colG - (seg << 9);
                __half* dst = (seg == 0) ? Ch : (seg == 1 ? Ck : Cv);
                int doPad = (seg != 0) && padKV;
                size_t o1 = doPad ? ((size_t)(r1 >> 12) * TP + 64 + (r1 & 4095)) : (size_t)r1;
                size_t o2 = doPad ? ((size_t)(r2 >> 12) * TP + 64 + (r2 & 4095)) : (size_t)r2;
                *(uint32_t*)(dst + o1 * 512 + colLoc) = packh(v0, v1);
                *(uint32_t*)(dst + o2 * 512 + colLoc) = packh(v2, v3);
            } else {
                float m1 = pm[r1] ? 1.0f : 0.0f;
                float m2 = pm[r2] ? 1.0f : 0.0f;
                const float* rr1 = R + (size_t)r1 * Nt + colG;
                const float* rr2 = R + (size_t)r2 * Nt + colG;
                float2 w1; w1.x = (v0 + rr1[0]) * m1; w1.y = (v1 + rr1[1]) * m1;
                float2 w2; w2.x = (v2 + rr2[0]) * m2; w2.y = (v3 + rr2[1]) * m2;
                *(float2*)(Cf + (size_t)r1 * Nt + colG) = w1;
                *(float2*)(Cf + (size_t)r2 * Nt + colG) = w2;
            }
        }
    }
}

// ---------------- weight convert ----------------
struct WPtrs { const float* p[11]; };
__global__ void cvt_w_kernel(WPtrs wp) {
    const int sizes[11] = {262144,262144,262144,262144,262144,262144,262144,262144,
                           524288,1048576,524288};
    const int offs[11]  = {0,262144,524288, 786432,1048576,1310720,
                           1572864,1835008, 2097152,2621440,3670016};
    int wi = blockIdx.y;
    int i4 = blockIdx.x * blockDim.x + threadIdx.x;
    if (i4 >= (sizes[wi] >> 2)) return;
    float4 v = ((const float4*)wp.p[wi])[i4];
    ((uint2*)(g_w + offs[wi]))[i4] = pack4h(v);
}

// ---------------- local rope tables + bias concat (merged setup) ----------------
struct BPtrs { const float* p[6]; };
__global__ void rope_init_kernel(BPtrs bp) {
    int idx = blockIdx.x * blockDim.x + threadIdx.x;
    if (idx < 256 * 64) {
        int t = idx >> 6, d = idx & 63;
        double inv = pow(10000.0, -(double)(d & 31) / 32.0);
        double a = (double)t * inv;
        g_lcos[idx] = (float)cos(a);
        g_lsin[idx] = (float)sin(a);
    }
    if (idx < 512) {
        #pragma unroll
        for (int i = 0; i < 6; i++)
            g_bcat[i * 512 + idx] = bp.p[i][idx];
    }
}

// ---------------- layernorm -> fp16 (optional fused input mask + residual copy) ----------------
__global__ void __launch_bounds__(128) ln_kernel(
    const float* __restrict__ X, const float* __restrict__ g,
    const float* __restrict__ b, const int* __restrict__ pm,
    __half* __restrict__ Yh, float* __restrict__ Xout,
    int maskIn, int maskOut)
{
    int row = blockIdx.x;
    int tid = threadIdx.x;
    float4 v = ((const float4*)(X + (size_t)row * DD))[tid];
    float mrow = pm[row] ? 1.0f : 0.0f;
    if (maskIn) {
        v.x *= mrow; v.y *= mrow; v.z *= mrow; v.w *= mrow;
        ((float4*)(Xout + (size_t)row * DD))[tid] = v;
    }
    float s  = v.x + v.y + v.z + v.w;
    float ss = v.x*v.x + v.y*v.y + v.z*v.z + v.w*v.w;
    #pragma unroll
    for (int o = 16; o; o >>= 1) {
        s  += __shfl_xor_sync(~0u, s,  o);
        ss += __shfl_xor_sync(~0u, ss, o);
    }
    __shared__ float sh[8];
    int w = tid >> 5, lane = tid & 31;
    if (lane == 0) { sh[w] = s; sh[4 + w] = ss; }
    __syncthreads();
    s  = sh[0] + sh[1] + sh[2] + sh[3];
    ss = sh[4] + sh[5] + sh[6] + sh[7];
    float mean = s * (1.0f / 512.0f);
    float var  = ss * (1.0f / 512.0f) - mean * mean;
    float inv  = rsqrtf(var + 1e-5f);
    float m = maskOut ? mrow : 1.0f;
    float4 gg = ((const float4*)g)[tid];
    float4 bb = ((const float4*)b)[tid];
    float4 o;
    o.x = ((v.x - mean) * inv * gg.x + bb.x) * m;
    o.y = ((v.y - mean) * inv * gg.y + bb.y) * m;
    o.z = ((v.z - mean) * inv * gg.z + bb.z) * m;
    o.w = ((v.w - mean) * inv * gg.w + bb.w) * m;
    ((uint2*)(Yh + (size_t)row * DD))[tid] = pack4h(o);
}

// ---------------- fill pad rows (fp16) ----------------
__global__ void fill_pad_kernel(const float* __restrict__ kb, const float* __restrict__ vb) {
    int idx = blockIdx.x * blockDim.x + threadIdx.x;
    if (idx >= BB * 128 * DD) return;
    int c  = idx & 511;
    int rr = (idx >> 9) & 127;
    int b  = idx >> 16;
    int prow = (rr < 64) ? rr : (TT + rr);
    size_t o = ((size_t)b * TP + prow) * DD + c;
    g_kp[o] = __float2half(kb[c]);
    g_vp[o] = __float2half(vb[c]);
}

// ---------------- local attention (mma, online softmax over 4 chunks of 64 keys) ----------------
#define ATS 72
__global__ void __launch_bounds__(256, 1) local_attn_kernel(
    const __half* __restrict__ Qg, const int* __restrict__ pm,
    __half* __restrict__ Og)
{
    int j = blockIdx.x, h = blockIdx.y, b = blockIdx.z;
    extern __shared__ char smc[];
    __half* Ks = (__half*)smc;                 // 256 x 72
    __half* Vs = Ks + 256 * ATS;               // 256 x 72
    __half* Qs = Vs + 256 * ATS;               // 128 x 72
    float* keepneg = (float*)(Qs + 128 * ATS); // 256
    int tid = threadIdx.x, lane = tid & 31;

    // load K (rope, vectorized 4-half) and V
    #pragma unroll 2
    for (int it = 0; it < 16; it++) {
        int idx = tid + it * 256;
        int r = idx >> 4, d = (idx & 15) * 4;
        size_t base = ((size_t)b * TP + (size_t)j * 128 + r) * DD + h * HD;
        float4 cs = *(const float4*)&g_lcos[r * 64 + d];
        float4 sn = *(const float4*)&g_lsin[r * 64 + d];
        float kv[4], ko[4];
        unpack4h(*(const uint2*)&g_kp[base + d], kv);
        unpack4h(*(const uint2*)&g_kp[base + (d ^ 32)], ko);
        float sg = (d < 32) ? -1.0f : 1.0f;
        float4 ro;
        ro.x = kv[0] * cs.x + sg * ko[0] * sn.x;
        ro.y = kv[1] * cs.y + sg * ko[1] * sn.y;
        ro.z = kv[2] * cs.z + sg * ko[2] * sn.z;
        ro.w = kv[3] * cs.w + sg * ko[3] * sn.w;
        *(uint2*)&Ks[r * ATS + d] = pack4h(ro);
        *(uint2*)&Vs[r * ATS + d] = *(const uint2*)&g_vp[base + d];
    }
    // load Q (rope, vectorized)
    #pragma unroll 2
    for (int it = 0; it < 8; it++) {
        int idx = tid + it * 256;
        int r = idx >> 4, d = (idx & 15) * 4;
        size_t base = ((size_t)b * TT + (size_t)j * 128 + r) * DD + h * HD;
        int ti = 64 + r;
        float4 cs = *(const float4*)&g_lcos[ti * 64 + d];
        float4 sn = *(const float4*)&g_lsin[ti * 64 + d];
        float qv[4], qo[4];
        unpack4h(*(const uint2*)&Qg[base + d], qv);
        unpack4h(*(const uint2*)&Qg[base + (d ^ 32)], qo);
        float sg = (d < 32) ? -1.0f : 1.0f;
        float4 ro;
        ro.x = qv[0] * cs.x + sg * qo[0] * sn.x;
        ro.y = qv[1] * cs.y + sg * qo[1] * sn.y;
        ro.z = qv[2] * cs.z + sg * qo[2] * sn.z;
        ro.w = qv[3] * cs.w + sg * qo[3] * sn.w;
        *(uint2*)&Qs[r * ATS + d] = pack4h(ro);
    }
    if (tid < 256) {
        int orig = j * 128 + tid - 64;
        keepneg[tid] = (orig >= 0 && orig < TT && pm[(size_t)b * TT + orig]) ? 0.0f : -1e9f;
    }
    __syncthreads();
    if (tid == 0) {
        int any = 0;
        for (int i = 0; i < 256; i++) any |= (keepneg[i] == 0.0f);
        if (!any) keepneg[0] = 0.0f;
    }
    __syncthreads();

    int m0 = (tid >> 5) * 16;
    float O[8][4];
    #pragma unroll
    for (int n = 0; n < 8; n++)
        #pragma unroll
        for (int c = 0; c < 4; c++) O[n][c] = 0.0f;
    float mr_lo = -1e30f, mr_hi = -1e30f, sr_lo = 0.0f, sr_hi = 0.0f;

    uint32_t qbase = smem_u32(Qs) + (uint32_t)(((m0 + (lane & 15)) * ATS + ((lane >> 4) << 3)) * 2);
    uint32_t kbaseS = smem_u32(Ks);
    uint32_t vbaseS = smem_u32(Vs);
    uint32_t krow = (lane & 7) + ((lane >> 4) & 1) * 8;
    uint32_t kcol = ((lane >> 3) & 1) * 8;
    uint32_t vrow = (lane & 15);
    uint32_t vcol = (lane >> 4) * 8;

    for (int ck = 0; ck < 4; ck++) {
        int k0 = ck * 64;
        float S[8][4];
        #pragma unroll
        for (int n = 0; n < 8; n++)
            #pragma unroll
            for (int c = 0; c < 4; c++) S[n][c] = 0.0f;
        #pragma unroll
        for (int kt = 0; kt < 4; kt++) {
            uint32_t aq[4];
            ldsm4(aq, qbase + kt * 32);
            #pragma unroll
            for (int ntp = 0; ntp < 4; ntp++) {
                uint32_t bk[4];
                ldsm4(bk, kbaseS + (uint32_t)(((k0 + ntp * 16 + krow) * ATS + kt * 16 + kcol) * 2));
                mma_f16(S[2*ntp],   aq, bk[0], bk[1]);
                mma_f16(S[2*ntp+1], aq, bk[2], bk[3]);
            }
        }
        float cm_lo = -1e30f, cm_hi = -1e30f;
        #pragma unroll
        for (int nt = 0; nt < 8; nt++) {
            int colg = k0 + nt * 8 + (lane & 3) * 2;
            float kn0 = keepneg[colg], kn1 = keepneg[colg + 1];
            S[nt][0] = S[nt][0] * 0.125f + kn0;
            S[nt][1] = S[nt][1] * 0.125f + kn1;
            S[nt][2] = S[nt][2] * 0.125f + kn0;
            S[nt][3] = S[nt][3] * 0.125f + kn1;
            cm_lo = fmaxf(cm_lo, fmaxf(S[nt][0], S[nt][1]));
            cm_hi = fmaxf(cm_hi, fmaxf(S[nt][2], S[nt][3]));
        }
        cm_lo = fmaxf(cm_lo, __shfl_xor_sync(~0u, cm_lo, 1));
        cm_lo = fmaxf(cm_lo, __shfl_xor_sync(~0u, cm_lo, 2));
        cm_hi = fmaxf(cm_hi, __shfl_xor_sync(~0u, cm_hi, 1));
        cm_hi = fmaxf(cm_hi, __shfl_xor_sync(~0u, cm_hi, 2));
        float mn_lo = fmaxf(mr_lo, cm_lo), mn_hi = fmaxf(mr_hi, cm_hi);
        float al_lo = __expf(mr_lo - mn_lo), al_hi = __expf(mr_hi - mn_hi);
        mr_lo = mn_lo; mr_hi = mn_hi;
        sr_lo *= al_lo; sr_hi *= al_hi;
        #pragma unroll
        for (int n = 0; n < 8; n++) {
            O[n][0] *= al_lo; O[n][1] *= al_lo;
            O[n][2] *= al_hi; O[n][3] *= al_hi;
        }
        uint32_t pa[4][4];
        #pragma unroll
        for (int kt = 0; kt < 4; kt++) {
            int t0 = 2 * kt, t1 = 2 * kt + 1;
            float p00 = __expf(S[t0][0] - mn_lo), p01 = __expf(S[t0][1] - mn_lo);
            float p02 = __expf(S[t0][2] - mn_hi), p03 = __expf(S[t0][3] - mn_hi);
            float p10 = __expf(S[t1][0] - mn_lo), p11 = __expf(S[t1][1] - mn_lo);
            float p12 = __expf(S[t1][2] - mn_hi), p13 = __expf(S[t1][3] - mn_hi);
            sr_lo += p00 + p01 + p10 + p11;
            sr_hi += p02 + p03 + p12 + p13;
            pa[kt][0] = packh(p00, p01);
            pa[kt][1] = packh(p02, p03);
            pa[kt][2] = packh(p10, p11);
            pa[kt][3] = packh(p12, p13);
        }
        #pragma unroll
        for (int kt = 0; kt < 4; kt++) {
            #pragma unroll
            for (int ntp = 0; ntp < 4; ntp++) {
                uint32_t vf[4];
                ldsm4t(vf, vbaseS + (uint32_t)(((k0 + kt * 16 + vrow) * ATS + ntp * 16 + vcol) * 2));
                mma_f16(O[2*ntp],   pa[kt], vf[0], vf[1]);
                mma_f16(O[2*ntp+1], pa[kt], vf[2], vf[3]);
            }
        }
    }
    sr_lo += __shfl_xor_sync(~0u, sr_lo, 1);
    sr_lo += __shfl_xor_sync(~0u, sr_lo, 2);
    sr_hi += __shfl_xor_sync(~0u, sr_hi, 1);
    sr_hi += __shfl_xor_sync(~0u, sr_hi, 2);
    float inv_lo = 1.0f / sr_lo, inv_hi = 1.0f / sr_hi;

    int r_lo = j * 128 + m0 + (lane >> 2);
    int r_hi = r_lo + 8;
    size_t b_lo = ((size_t)b * TT + r_lo) * DD + h * HD;
    size_t b_hi = ((size_t)b * TT + r_hi) * DD + h * HD;
    #pragma unroll
    for (int nt = 0; nt < 8; nt++) {
        int col = nt * 8 + (lane & 3) * 2;
        *(uint32_t*)&Og[b_lo + col] = packh(O[nt][0] * inv_lo, O[nt][1] * inv_lo);
        *(uint32_t*)&Og[b_hi + col] = packh(O[nt][2] * inv_hi, O[nt][3] * inv_hi);
    }
}

// ---------------- global (dilated) attention (mma, single 64-key tile) ----------------
__global__ void __launch_bounds__(128, 1) global_attn_kernel(
    const __half* __restrict__ Qg, const __half* __restrict__ Kg,
    const __half* __restrict__ Vg, const int* __restrict__ pm,
    const float* __restrict__ cosp, const float* __restrict__ sinp,
    __half* __restrict__ Og)
{
    int w = blockIdx.x, h = blockIdx.y, b = blockIdx.z;
    extern __shared__ char smc[];
    __half* Qs = (__half*)smc;                 // 64 x 72
    __half* Ks = Qs + 64 * ATS;
    __half* Vs = Ks + 64 * ATS;
    float* keepneg = (float*)(Vs + 64 * ATS);  // 64
    int tid = threadIdx.x, lane = tid & 31;

    #pragma unroll 2
    for (int it = 0; it < 8; it++) {
        int idx = tid + it * 128;
        int r = idx >> 4, d = (idx & 15) * 4;
        int p = r * 64 + w;
        size_t base = ((size_t)b * TT + p) * DD + h * HD;
        float4 cs = *(const float4*)&cosp[p * 64 + d];
        float4 sn = *(const float4*)&sinp[p * 64 + d];
        float qv[4], qo[4], kv[4], ko[4];
        unpack4h(*(const uint2*)&Qg[base + d], qv);
        unpack4h(*(const uint2*)&Qg[base + (d ^ 32)], qo);
        unpack4h(*(const uint2*)&Kg[base + d], kv);
        unpack4h(*(const uint2*)&Kg[base + (d ^ 32)], ko);
        float sg = (d < 32) ? -1.0f : 1.0f;
        float4 qr, kr;
        qr.x = qv[0] * cs.x + sg * qo[0] * sn.x;
        qr.y = qv[1] * cs.y + sg * qo[1] * sn.y;
        qr.z = qv[2] * cs.z + sg * qo[2] * sn.z;
        qr.w = qv[3] * cs.w + sg * qo[3] * sn.w;
        kr.x = kv[0] * cs.x + sg * ko[0] * sn.x;
        kr.y = kv[1] * cs.y + sg * ko[1] * sn.y;
        kr.z = kv[2] * cs.z + sg * ko[2] * sn.z;
        kr.w = kv[3] * cs.w + sg * ko[3] * sn.w;
        *(uint2*)&Qs[r * ATS + d] = pack4h(qr);
        *(uint2*)&Ks[r * ATS + d] = pack4h(kr);
        *(uint2*)&Vs[r * ATS + d] = *(const uint2*)&Vg[base + d];
    }
    if (tid < 64) keepneg[tid] = pm[(size_t)b * TT + tid * 64 + w] ? 0.0f : -1e9f;
    __syncthreads();

    int m0 = (tid >> 5) * 16;
    uint32_t qbase = smem_u32(Qs) + (uint32_t)(((m0 + (lane & 15)) * ATS + ((lane >> 4) << 3)) * 2);
    uint32_t kbaseS = smem_u32(Ks);
    uint32_t vbaseS = smem_u32(Vs);
    uint32_t krow = (lane & 7) + ((lane >> 4) & 1) * 8;
    uint32_t kcol = ((lane >> 3) & 1) * 8;
    uint32_t vrow = (lane & 15);
    uint32_t vcol = (lane >> 4) * 8;

    float S[8][4];
    #pragma unroll
    for (int n = 0; n < 8; n++)
        #pragma unroll
        for (int c = 0; c < 4; c++) S[n][c] = 0.0f;
    #pragma unroll
    for (int kt = 0; kt < 4; kt++) {
        uint32_t aq[4];
        ldsm4(aq, qbase + kt * 32);
        #pragma unroll
        for (int ntp = 0; ntp < 4; ntp++) {
            uint32_t bk[4];
            ldsm4(bk, kbaseS + (uint32_t)(((ntp * 16 + krow) * ATS + kt * 16 + kcol) * 2));
            mma_f16(S[2*ntp],   aq, bk[0], bk[1]);
            mma_f16(S[2*ntp+1], aq, bk[2], bk[3]);
        }
    }
    float cm_lo = -1e30f, cm_hi = -1e30f;
    #pragma unroll
    for (int nt = 0; nt < 8; nt++) {
        int colg = nt * 8 + (lane & 3) * 2;
        float kn0 = keepneg[colg], kn1 = keepneg[colg + 1];
        S[nt][0] = S[nt][0] * 0.125f + kn0;
        S[nt][1] = S[nt][1] * 0.125f + kn1;
        S[nt][2] = S[nt][2] * 0.125f + kn0;
        S[nt][3] = S[nt][3] * 0.125f + kn1;
        cm_lo = fmaxf(cm_lo, fmaxf(S[nt][0], S[nt][1]));
        cm_hi = fmaxf(cm_hi, fmaxf(S[nt][2], S[nt][3]));
    }
    cm_lo = fmaxf(cm_lo, __shfl_xor_sync(~0u, cm_lo, 1));
    cm_lo = fmaxf(cm_lo, __shfl_xor_sync(~0u, cm_lo, 2));
    cm_hi = fmaxf(cm_hi, __shfl_xor_sync(~0u, cm_hi, 1));
    cm_hi = fmaxf(cm_hi, __shfl_xor_sync(~0u, cm_hi, 2));

    float sr_lo = 0.0f, sr_hi = 0.0f;
    uint32_t pa[4][4];
    float O[8][4];
    #pragma unroll
    for (int n = 0; n < 8; n++)
        #pragma unroll
        for (int c = 0; c < 4; c++) O[n][c] = 0.0f;
    #pragma unroll
    for (int kt = 0; kt < 4; kt++) {
        int t0 = 2 * kt, t1 = 2 * kt + 1;
        float p00 = __expf(S[t0][0] - cm_lo), p01 = __expf(S[t0][1] - cm_lo);
        float p02 = __expf(S[t0][2] - cm_hi), p03 = __expf(S[t0][3] - cm_hi);
        float p10 = __expf(S[t1][0] - cm_lo), p11 = __expf(S[t1][1] - cm_lo);
        float p12 = __expf(S[t1][2] - cm_hi), p13 = __expf(S[t1][3] - cm_hi);
        sr_lo += p00 + p01 + p10 + p11;
        sr_hi += p02 + p03 + p12 + p13;
        pa[kt][0] = packh(p00, p01);
        pa[kt][1] = packh(p02, p03);
        pa[kt][2] = packh(p10, p11);
        pa[kt][3] = packh(p12, p13);
    }
    #pragma unroll
    for (int kt = 0; kt < 4; kt++) {
        #pragma unroll
        for (int ntp = 0; ntp < 4; ntp++) {
            uint32_t vf[4];
            ldsm4t(vf, vbaseS + (uint32_t)(((kt * 16 + vrow) * ATS + ntp * 16 + vcol) * 2));
            mma_f16(O[2*ntp],   pa[kt], vf[0], vf[1]);
            mma_f16(O[2*ntp+1], pa[kt], vf[2], vf[3]);
        }
    }
    sr_lo += __shfl_xor_sync(~0u, sr_lo, 1);
    sr_lo += __shfl_xor_sync(~0u, sr_lo, 2);
    sr_hi += __shfl_xor_sync(~0u, sr_hi, 1);
    sr_hi += __shfl_xor_sync(~0u, sr_hi, 2);
    float inv_lo = 1.0f / sr_lo, inv_hi = 1.0f / sr_hi;

    int p_lo = (m0 + (lane >> 2)) * 64 + w;
    int p_hi = p_lo + 8 * 64;
    size_t b_lo = ((size_t)b * TT + p_lo) * DD + h * HD;
    size_t b_hi = ((size_t)b * TT + p_hi) * DD + h * HD;
    #pragma unroll
    for (int nt = 0; nt < 8; nt++) {
        int col = nt * 8 + (lane & 3) * 2;
        *(uint32_t*)&Og[b_lo + col] = packh(O[nt][0] * inv_lo, O[nt][1] * inv_lo);
        *(uint32_t*)&Og[b_hi + col] = packh(O[nt][2] * inv_hi, O[nt][3] * inv_hi);
    }
}

// ---------------- host ----------------
extern "C" void kernel_launch(void* const* d_in, const int* in_sizes, int n_in,
                              void* d_out, int out_size)
{
    const float* x    = (const float*)d_in[0];
    const int*   pm   = (const int*)d_in[1];
    const float* cosp = (const float*)d_in[2];
    const float* sinp = (const float*)d_in[3];
    const float* ln1_g = (const float*)d_in[4];
    const float* ln1_b = (const float*)d_in[5];
    const float* ln2_g = (const float*)d_in[6];
    const float* ln2_b = (const float*)d_in[7];
    const float* ln3_g = (const float*)d_in[8];
    const float* ln3_b = (const float*)d_in[9];
    const float* lq_w = (const float*)d_in[10];
    const float* lq_b = (const float*)d_in[11];
    const float* lk_w = (const float*)d_in[12];
    const float* lk_b = (const float*)d_in[13];
    const float* lv_w = (const float*)d_in[14];
    const float* lv_b = (const float*)d_in[15];
    const float* lo_w = (const float*)d_in[16];
    const float* lo_b = (const float*)d_in[17];
    const float* gq_w = (const float*)d_in[18];
    const float* gq_b = (const float*)d_in[19];
    const float* gk_w = (const float*)d_in[20];
    const float* gk_b = (const float*)d_in[21];
    const float* gv_w = (const float*)d_in[22];
    const float* gv_b = (const float*)d_in[23];
    const float* go_w = (const float*)d_in[24];
    const float* go_b = (const float*)d_in[25];
    const float* f1_w = (const float*)d_in[26];
    const float* f1_b = (const float*)d_in[27];
    const float* f2_w = (const float*)d_in[28];
    const float* f2_b = (const float*)d_in[29];
    const float* f3_w = (const float*)d_in[30];
    const float* f3_b = (const float*)d_in[31];
    float* out = (float*)d_out;

    float *px, *pbcat;
    __half *pq, *pkp, *pvp, *pxn, *patt, *ph1, *ph2, *pw;
    cudaGetSymbolAddress((void**)&px,    g_x);
    cudaGetSymbolAddress((void**)&pq,    g_q);
    cudaGetSymbolAddress((void**)&pkp,   g_kp);
    cudaGetSymbolAddress((void**)&pvp,   g_vp);
    cudaGetSymbolAddress((void**)&pbcat, g_bcat);
    cudaGetSymbolAddress((void**)&pxn,   g_xn);
    cudaGetSymbolAddress((void**)&patt,  g_att);
    cudaGetSymbolAddress((void**)&ph1,   g_h1);
    cudaGetSymbolAddress((void**)&ph2,   g_h2);
    cudaGetSymbolAddress((void**)&pw,    g_w);

    const int M = BB * TT;
    const int EW = 256;

    size_t smLoc = (size_t)(2 * 256 * ATS + 128 * ATS) * 2 + 256 * 4;
    size_t smGlb = (size_t)(3 * 64 * ATS) * 2 + 64 * 4;
    size_t smGemm = 3 * GSTG;
    cudaFuncSetAttribute(local_attn_kernel,  cudaFuncAttributeMaxDynamicSharedMemorySize, (int)smLoc);
    cudaFuncSetAttribute(global_attn_kernel, cudaFuncAttributeMaxDynamicSharedMemorySize, (int)smGlb);
    cudaFuncSetAttribute(gemm_mma_kernel, cudaFuncAttributeMaxDynamicSharedMemorySize, (int)smGemm);

    const int OLQKV=0, OGQKV=786432, OLO=1572864, OGO=1835008,
              OF1=2097152, OF2=2621440, OF3=3670016;

    dim3 gQKV(6, M / 128);
    dim3 g512(2, M / 128);
    dim3 g1k (4, M / 128);

    BPtrs bp;
    bp.p[0]=lq_b; bp.p[1]=lk_b; bp.p[2]=lv_b; bp.p[3]=gq_b; bp.p[4]=gk_b; bp.p[5]=gv_b;
    rope_init_kernel<<<64, 256>>>(bp);
    WPtrs wp;
    wp.p[0]=lq_w; wp.p[1]=lk_w; wp.p[2]=lv_w; wp.p[3]=gq_w; wp.p[4]=gk_w;
    wp.p[5]=gv_w; wp.p[6]=lo_w; wp.p[7]=go_w; wp.p[8]=f1_w; wp.p[9]=f2_w; wp.p[10]=f3_w;
    cvt_w_kernel<<<dim3(1024, 11), 256>>>(wp);

    // fused: px = x*mask; xn = LN(px)*mask
    ln_kernel<<<M, 128>>>(x, ln1_g, ln1_b, pm, pxn, px, 1, 1);

    // local QKV fused (q plain fp16, k/v padded fp16)
    gemm_mma_kernel<<<gQKV, 512, smGemm>>>(pxn, pw+OLQKV, pbcat,
                                           0, pq, pkp, pvp, 0, 0, DD, DD, 0, 2, 1);
    fill_pad_kernel<<<(BB * 128 * DD + EW - 1) / EW, EW>>>(lk_b, lv_b);

    local_attn_kernel<<<dim3(NLOC, HH, BB), 256, smLoc>>>(pq, pm, patt);

    // O proj + residual + mask (in place on px)
    gemm_mma_kernel<<<g512, 512, smGemm>>>(patt, pw+OLO, lo_b,
                                           px, 0, 0, 0, px, pm, DD, DD, 0, 3, 0);

    ln_kernel<<<M, 128>>>(px, ln2_g, ln2_b, pm, pxn, 0, 0, 0);

    // global QKV fused (plain fp16)
    gemm_mma_kernel<<<gQKV, 512, smGemm>>>(pxn, pw+OGQKV, pbcat + 1536,
                                           0, pq, pkp, pvp, 0, 0, DD, DD, 0, 2, 0);

    global_attn_kernel<<<dim3(NDIL, HH, BB), 128, smGlb>>>(pq, pkp, pvp, pm, cosp, sinp, patt);

    gemm_mma_kernel<<<g512, 512, smGemm>>>(patt, pw+OGO, go_b,
                                           px, 0, 0, 0, px, pm, DD, DD, 0, 3, 0);

    ln_kernel<<<M, 128>>>(px, ln3_g, ln3_b, pm, pxn, 0, 0, 0);
    gemm_mma_kernel<<<g1k,  512, smGemm>>>(pxn, pw+OF1, f1_b,
                                           0, ph1, 0, 0, 0, 0, 512,  1024, 1, 1, 0);
    gemm_mma_kernel<<<g1k,  512, smGemm>>>(ph1, pw+OF2, f2_b,
                                           0, ph2, 0, 0, 0, 0, 1024, 1024, 1, 1, 0);
    // f3 + residual + mask -> out
    gemm_mma_kernel<<<g512, 512, smGemm>>>(ph2, pw+OF3, f3_b,
                                           out, 0, 0, 0, px, pm, 1024, 512, 0, 3, 0);
}

// round 17
// speedup vs baseline: 1.0417x; 1.0297x over previous
#include <cuda_runtime.h>
#include <cuda_bf16.h>
#include <cuda_fp16.h>
#include <math.h>
#include <stdint.h>

#define BB 8
#define TT 4096
#define DD 512
#define HH 8
#define HD 64
#define TP 4224
#define NLOC 32
#define NDIL 64

// ---------------- scratch ----------------
__device__ __half g_xh [BB*TT*DD];   // residual stream (fp16)
__device__ __half g_q  [BB*TT*DD];
__device__ __half g_kp [BB*TP*DD];
__device__ __half g_vp [BB*TP*DD];
__device__ __half g_xn [BB*TT*DD];
__device__ __half g_att[BB*TT*DD];
__device__ __half g_h1 [BB*TT*1024];
__device__ __half g_h2 [BB*TT*1024];
__device__ __half g_w  [4194304];
__device__ float g_bcat[3072];
__device__ float g_lcos[256*64];
__device__ float g_lsin[256*64];

// ---------------- helpers ----------------
__device__ __forceinline__ uint32_t smem_u32(const void* p) {
    uint32_t a;
    asm("{ .reg .u64 t; cvta.to.shared.u64 t, %1; cvt.u32.u64 %0, t; }" : "=r"(a) : "l"(p));
    return a;
}
__device__ __forceinline__ void ldsm4(uint32_t* r, uint32_t addr) {
    asm volatile("ldmatrix.sync.aligned.m8n8.x4.shared.b16 {%0,%1,%2,%3}, [%4];"
        : "=r"(r[0]), "=r"(r[1]), "=r"(r[2]), "=r"(r[3]) : "r"(addr));
}
__device__ __forceinline__ void ldsm4t(uint32_t* r, uint32_t addr) {
    asm volatile("ldmatrix.sync.aligned.m8n8.x4.trans.shared.b16 {%0,%1,%2,%3}, [%4];"
        : "=r"(r[0]), "=r"(r[1]), "=r"(r[2]), "=r"(r[3]) : "r"(addr));
}
__device__ __forceinline__ void mma_f16(float* c, const uint32_t* a, uint32_t b0, uint32_t b1) {
    asm volatile("mma.sync.aligned.m16n8k16.row.col.f32.f16.f16.f32 "
        "{%0,%1,%2,%3}, {%4,%5,%6,%7}, {%8,%9}, {%0,%1,%2,%3};"
        : "+f"(c[0]), "+f"(c[1]), "+f"(c[2]), "+f"(c[3])
        : "r"(a[0]), "r"(a[1]), "r"(a[2]), "r"(a[3]), "r"(b0), "r"(b1));
}
#define SWZ64(x) ((x) ^ (((x) >> 3) & 0x30))
#define CPA(dst, src) asm volatile("cp.async.cg.shared.global [%0], [%1], 16;" :: "r"(dst), "l"(src))
#define CPC() asm volatile("cp.async.commit_group;" ::: "memory")
#define CPW(n) asm volatile("cp.async.wait_group %0;" :: "n"(n) : "memory")

__device__ __forceinline__ uint32_t packh(float a, float b) {
    __half2 h = __floats2half2_rn(a, b);
    return *(uint32_t*)&h;
}
__device__ __forceinline__ uint2 pack4h(float4 v) {
    uint2 r; r.x = packh(v.x, v.y); r.y = packh(v.z, v.w); return r;
}
__device__ __forceinline__ void unpack4h(uint2 u, float* f) {
    __half2 a = *(__half2*)&u.x, b = *(__half2*)&u.y;
    f[0] = __low2float(a); f[1] = __high2float(a);
    f[2] = __low2float(b); f[3] = __high2float(b);
}
__device__ __forceinline__ void unpack2h(uint32_t u, float& a, float& b) {
    __half2 h = *(__half2*)&u;
    a = __low2float(h); b = __high2float(h);
}

// ---------------- GEMM (fp16): CTA 128x256, warp tile 32x64, BK=64, 3-stage ----------------
// modes: 1=fp16 out, 2=QKV triple (fp16), 3=fp32 out + fp16 residual + mask, 4=fp16 out + fp16 residual + mask
#define GSTG 49152
__global__ void __launch_bounds__(512, 1) gemm_mma_kernel(
    const __half* __restrict__ A, const __half* __restrict__ W,
    const float* __restrict__ bias,
    float* __restrict__ Cf, __half* __restrict__ Ch,
    __half* __restrict__ Ck, __half* __restrict__ Cv,
    const __half* __restrict__ Rh, const int* __restrict__ pm,
    int K, int Nt, int act, int mode, int padKV)
{
    extern __shared__ char sm[];
    uint32_t smb = smem_u32(sm);
    int tid = threadIdx.x, lane = tid & 31, wid = tid >> 5;
    int row0 = blockIdx.y * 128, col0 = blockIdx.x * 256;
    int wm = (wid & 3) * 32, wn = (wid >> 2) * 64;

    float acc[2][8][4];
    #pragma unroll
    for (int i = 0; i < 2; i++)
        #pragma unroll
        for (int j = 0; j < 8; j++)
            #pragma unroll
            for (int c = 0; c < 4; c++) acc[i][j][c] = 0.0f;

    int srow = tid >> 2, sc = tid & 3;
    uint32_t sdA  = SWZ64((uint32_t)(srow * 64 + sc * 16));
    uint32_t sdW0 = sdA;
    uint32_t sdW1 = SWZ64((uint32_t)((128 + srow) * 64 + sc * 16));
    size_t gA  = (size_t)(row0 + srow) * K + sc * 8;
    size_t gW0 = (size_t)(col0 + srow) * K + sc * 8;
    size_t gW1 = (size_t)(col0 + 128 + srow) * K + sc * 8;

    uint32_t aoff[2], boff[4];
    #pragma unroll
    for (int i = 0; i < 2; i++) {
        int r = wm + i * 16 + (lane & 15);
        aoff[i] = r * 64 + ((lane >> 4) << 4);
    }
    #pragma unroll
    for (int j = 0; j < 4; j++) {
        int r = wn + j * 16 + (lane & 7) + ((lane >> 4) & 1) * 8;
        boff[j] = r * 64 + (((lane >> 3) & 1) << 4);
    }

    int nch = K >> 6;
    #define G_ISSUE(ch) { \
        uint32_t st_ = smb + ((ch) % 3) * GSTG; \
        size_t k0_ = (size_t)(ch) * 64; \
        CPA(st_ + sdA,                  A + gA  + k0_); \
        CPA(st_ + 8192 + sdW0,          W + gW0 + k0_); \
        CPA(st_ + 8192 + sdW1,          W + gW1 + k0_); \
        CPA(st_ + 24576 + sdA,          A + gA  + k0_ + 32); \
        CPA(st_ + 24576 + 8192 + sdW0,  W + gW0 + k0_ + 32); \
        CPA(st_ + 24576 + 8192 + sdW1,  W + gW1 + k0_ + 32); \
        CPC(); }

    G_ISSUE(0);
    if (nch > 1) G_ISSUE(1);

    for (int ch = 0; ch < nch; ch++) {
        if (ch + 1 < nch) { CPW(1); } else { CPW(0); }
        __syncthreads();
        if (ch + 2 < nch) G_ISSUE(ch + 2);
        uint32_t st = smb + (ch % 3) * GSTG;
        #pragma unroll
        for (int sub = 0; sub < 2; sub++) {
            uint32_t sA = st + sub * 24576;
            uint32_t sW = sA + 8192;
            #pragma unroll
            for (int ks = 0; ks < 2; ks++) {
                uint32_t ah[2][4], bh[4][4];
                #pragma unroll
                for (int i = 0; i < 2; i++)
                    ldsm4(ah[i], sA + SWZ64(aoff[i] + ks * 32));
                #pragma unroll
                for (int j = 0; j < 4; j++)
                    ldsm4(bh[j], sW + SWZ64(boff[j] + ks * 32));
                #pragma unroll
                for (int i = 0; i < 2; i++)
                    #pragma unroll
                    for (int j = 0; j < 4; j++) {
                        mma_f16(acc[i][2*j],   ah[i], bh[j][0], bh[j][1]);
                        mma_f16(acc[i][2*j+1], ah[i], bh[j][2], bh[j][3]);
                    }
            }
        }
    }

    // epilogue
    int g = lane >> 2, t4 = lane & 3;
    #pragma unroll
    for (int i = 0; i < 2; i++) {
        int r1 = row0 + wm + i * 16 + g;
        int r2 = r1 + 8;
        #pragma unroll
        for (int nj = 0; nj < 8; nj++) {
            int colG = col0 + wn + nj * 8 + t4 * 2;
            float b0 = bias[colG], b1 = bias[colG + 1];
            float v0 = acc[i][nj][0] + b0, v1 = acc[i][nj][1] + b1;
            float v2 = acc[i][nj][2] + b0, v3 = acc[i][nj][3] + b1;
            if (act) {
                v0 = 0.5f * v0 * (1.0f + erff(v0 * 0.70710678118654752f));
                v1 = 0.5f * v1 * (1.0f + erff(v1 * 0.70710678118654752f));
                v2 = 0.5f * v2 * (1.0f + erff(v2 * 0.70710678118654752f));
                v3 = 0.5f * v3 * (1.0f + erff(v3 * 0.70710678118654752f));
            }
            if (mode == 1) {
                *(uint32_t*)(Ch + (size_t)r1 * Nt + colG) = packh(v0, v1);
                *(uint32_t*)(Ch + (size_t)r2 * Nt + colG) = packh(v2, v3);
            } else if (mode == 2) {
                int seg = colG >> 9;
                int colLoc = colG - (seg << 9);
                __half* dst = (seg == 0) ? Ch : (seg == 1 ? Ck : Cv);
                int doPad = (seg != 0) && padKV;
                size_t o1 = doPad ? ((size_t)(r1 >> 12) * TP + 64 + (r1 & 4095)) : (size_t)r1;
                size_t o2 = doPad ? ((size_t)(r2 >> 12) * TP + 64 + (r2 & 4095)) : (size_t)r2;
                *(uint32_t*)(dst + o1 * 512 + colLoc) = packh(v0, v1);
                *(uint32_t*)(dst + o2 * 512 + colLoc) = packh(v2, v3);
            } else {
                float m1 = pm[r1] ? 1.0f : 0.0f;
                float m2 = pm[r2] ? 1.0f : 0.0f;
                float ra0, ra1, rb0, rb1;
                unpack2h(*(const uint32_t*)(Rh + (size_t)r1 * Nt + colG), ra0, ra1);
                unpack2h(*(const uint32_t*)(Rh + (size_t)r2 * Nt + colG), rb0, rb1);
                float w10 = (v0 + ra0) * m1, w11 = (v1 + ra1) * m1;
                float w20 = (v2 + rb0) * m2, w21 = (v3 + rb1) * m2;
                if (mode == 3) {
                    float2 w1; w1.x = w10; w1.y = w11;
                    float2 w2; w2.x = w20; w2.y = w21;
                    *(float2*)(Cf + (size_t)r1 * Nt + colG) = w1;
                    *(float2*)(Cf + (size_t)r2 * Nt + colG) = w2;
                } else {
                    *(uint32_t*)(Ch + (size_t)r1 * Nt + colG) = packh(w10, w11);
                    *(uint32_t*)(Ch + (size_t)r2 * Nt + colG) = packh(w20, w21);
                }
            }
        }
    }
}

// ---------------- weight convert ----------------
struct WPtrs { const float* p[11]; };
__global__ void cvt_w_kernel(WPtrs wp) {
    const int sizes[11] = {262144,262144,262144,262144,262144,262144,262144,262144,
                           524288,1048576,524288};
    const int offs[11]  = {0,262144,524288, 786432,1048576,1310720,
                           1572864,1835008, 2097152,2621440,3670016};
    int wi = blockIdx.y;
    int i4 = blockIdx.x * blockDim.x + threadIdx.x;
    if (i4 >= (sizes[wi] >> 2)) return;
    float4 v = ((const float4*)wp.p[wi])[i4];
    ((uint2*)(g_w + offs[wi]))[i4] = pack4h(v);
}

// ---------------- merged setup: rope tables + bias concat + pad-row fill ----------------
struct BPtrs { const float* p[6]; };
__global__ void setup_kernel(BPtrs bp, const float* __restrict__ kb, const float* __restrict__ vb) {
    int idx = blockIdx.x * blockDim.x + threadIdx.x;  // 2048 * 256 = 524288
    if (idx < 256 * 64) {
        int t = idx >> 6, d = idx & 63;
        double inv = pow(10000.0, -(double)(d & 31) / 32.0);
        double a = (double)t * inv;
        g_lcos[idx] = (float)cos(a);
        g_lsin[idx] = (float)sin(a);
    }
    if (idx < 512) {
        #pragma unroll
        for (int i = 0; i < 6; i++)
            g_bcat[i * 512 + idx] = bp.p[i][idx];
    }
    // pad rows: BB*128*DD = 524288 elements
    {
        int c  = idx & 511;
        int rr = (idx >> 9) & 127;
        int b  = idx >> 16;
        int prow = (rr < 64) ? rr : (TT + rr);
        size_t o = ((size_t)b * TP + prow) * DD + c;
        g_kp[o] = __float2half(kb[c]);
        g_vp[o] = __float2half(vb[c]);
    }
}

// ---------------- layernorm -> fp16 (fp32 or fp16 input; optional fused mask + residual copy) ----
__global__ void __launch_bounds__(128) ln_kernel(
    const void* __restrict__ Xv, const float* __restrict__ g,
    const float* __restrict__ b, const int* __restrict__ pm,
    __half* __restrict__ Yh, __half* __restrict__ Xout,
    int maskIn, int maskOut, int inHalf)
{
    int row = blockIdx.x;
    int tid = threadIdx.x;
    float4 v;
    if (inHalf) {
        uint2 u = ((const uint2*)Xv)[(size_t)row * 128 + tid];
        float f[4];
        unpack4h(u, f);
        v.x = f[0]; v.y = f[1]; v.z = f[2]; v.w = f[3];
    } else {
        v = ((const float4*)Xv)[(size_t)row * 128 + tid];
    }
    float mrow = pm[row] ? 1.0f : 0.0f;
    if (maskIn) {
        v.x *= mrow; v.y *= mrow; v.z *= mrow; v.w *= mrow;
        ((uint2*)(Xout + (size_t)row * DD))[tid] = pack4h(v);
    }
    float s  = v.x + v.y + v.z + v.w;
    float ss = v.x*v.x + v.y*v.y + v.z*v.z + v.w*v.w;
    #pragma unroll
    for (int o = 16; o; o >>= 1) {
        s  += __shfl_xor_sync(~0u, s,  o);
        ss += __shfl_xor_sync(~0u, ss, o);
    }
    __shared__ float sh[8];
    int w = tid >> 5, lane = tid & 31;
    if (lane == 0) { sh[w] = s; sh[4 + w] = ss; }
    __syncthreads();
    s  = sh[0] + sh[1] + sh[2] + sh[3];
    ss = sh[4] + sh[5] + sh[6] + sh[7];
    float mean = s * (1.0f / 512.0f);
    float var  = ss * (1.0f / 512.0f) - mean * mean;
    float inv  = rsqrtf(var + 1e-5f);
    float m = maskOut ? mrow : 1.0f;
    float4 gg = ((const float4*)g)[tid];
    float4 bb = ((const float4*)b)[tid];
    float4 o;
    o.x = ((v.x - mean) * inv * gg.x + bb.x) * m;
    o.y = ((v.y - mean) * inv * gg.y + bb.y) * m;
    o.z = ((v.z - mean) * inv * gg.z + bb.z) * m;
    o.w = ((v.w - mean) * inv * gg.w + bb.w) * m;
    ((uint2*)(Yh + (size_t)row * DD))[tid] = pack4h(o);
}

// ---------------- local attention (mma, online softmax over 4 chunks of 64 keys) ----------------
#define ATS 72
__global__ void __launch_bounds__(256, 1) local_attn_kernel(
    const __half* __restrict__ Qg, const int* __restrict__ pm,
    __half* __restrict__ Og)
{
    int j = blockIdx.x, h = blockIdx.y, b = blockIdx.z;
    extern __shared__ char smc[];
    __half* Ks = (__half*)smc;
    __half* Vs = Ks + 256 * ATS;
    __half* Qs = Vs + 256 * ATS;
    float* keepneg = (float*)(Qs + 128 * ATS);
    int tid = threadIdx.x, lane = tid & 31;

    #pragma unroll 2
    for (int it = 0; it < 16; it++) {
        int idx = tid + it * 256;
        int r = idx >> 4, d = (idx & 15) * 4;
        size_t base = ((size_t)b * TP + (size_t)j * 128 + r) * DD + h * HD;
        float4 cs = *(const float4*)&g_lcos[r * 64 + d];
        float4 sn = *(const float4*)&g_lsin[r * 64 + d];
        float kv[4], ko[4];
        unpack4h(*(const uint2*)&g_kp[base + d], kv);
        unpack4h(*(const uint2*)&g_kp[base + (d ^ 32)], ko);
        float sg = (d < 32) ? -1.0f : 1.0f;
        float4 ro;
        ro.x = kv[0] * cs.x + sg * ko[0] * sn.x;
        ro.y = kv[1] * cs.y + sg * ko[1] * sn.y;
        ro.z = kv[2] * cs.z + sg * ko[2] * sn.z;
        ro.w = kv[3] * cs.w + sg * ko[3] * sn.w;
        *(uint2*)&Ks[r * ATS + d] = pack4h(ro);
        *(uint2*)&Vs[r * ATS + d] = *(const uint2*)&g_vp[base + d];
    }
    #pragma unroll 2
    for (int it = 0; it < 8; it++) {
        int idx = tid + it * 256;
        int r = idx >> 4, d = (idx & 15) * 4;
        size_t base = ((size_t)b * TT + (size_t)j * 128 + r) * DD + h * HD;
        int ti = 64 + r;
        float4 cs = *(const float4*)&g_lcos[ti * 64 + d];
        float4 sn = *(const float4*)&g_lsin[ti * 64 + d];
        float qv[4], qo[4];
        unpack4h(*(const uint2*)&Qg[base + d], qv);
        unpack4h(*(const uint2*)&Qg[base + (d ^ 32)], qo);
        float sg = (d < 32) ? -1.0f : 1.0f;
        float4 ro;
        ro.x = qv[0] * cs.x + sg * qo[0] * sn.x;
        ro.y = qv[1] * cs.y + sg * qo[1] * sn.y;
        ro.z = qv[2] * cs.z + sg * qo[2] * sn.z;
        ro.w = qv[3] * cs.w + sg * qo[3] * sn.w;
        *(uint2*)&Qs[r * ATS + d] = pack4h(ro);
    }
    if (tid < 256) {
        int orig = j * 128 + tid - 64;
        keepneg[tid] = (orig >= 0 && orig < TT && pm[(size_t)b * TT + orig]) ? 0.0f : -1e9f;
    }
    __syncthreads();
    if (tid == 0) {
        int any = 0;
        for (int i = 0; i < 256; i++) any |= (keepneg[i] == 0.0f);
        if (!any) keepneg[0] = 0.0f;
    }
    __syncthreads();

    int m0 = (tid >> 5) * 16;
    float O[8][4];
    #pragma unroll
    for (int n = 0; n < 8; n++)
        #pragma unroll
        for (int c = 0; c < 4; c++) O[n][c] = 0.0f;
    float mr_lo = -1e30f, mr_hi = -1e30f, sr_lo = 0.0f, sr_hi = 0.0f;

    uint32_t qbase = smem_u32(Qs) + (uint32_t)(((m0 + (lane & 15)) * ATS + ((lane >> 4) << 3)) * 2);
    uint32_t kbaseS = smem_u32(Ks);
    uint32_t vbaseS = smem_u32(Vs);
    uint32_t krow = (lane & 7) + ((lane >> 4) & 1) * 8;
    uint32_t kcol = ((lane >> 3) & 1) * 8;
    uint32_t vrow = (lane & 15);
    uint32_t vcol = (lane >> 4) * 8;

    for (int ck = 0; ck < 4; ck++) {
        int k0 = ck * 64;
        float S[8][4];
        #pragma unroll
        for (int n = 0; n < 8; n++)
            #pragma unroll
            for (int c = 0; c < 4; c++) S[n][c] = 0.0f;
        #pragma unroll
        for (int kt = 0; kt < 4; kt++) {
            uint32_t aq[4];
            ldsm4(aq, qbase + kt * 32);
            #pragma unroll
            for (int ntp = 0; ntp < 4; ntp++) {
                uint32_t bk[4];
                ldsm4(bk, kbaseS + (uint32_t)(((k0 + ntp * 16 + krow) * ATS + kt * 16 + kcol) * 2));
                mma_f16(S[2*ntp],   aq, bk[0], bk[1]);
                mma_f16(S[2*ntp+1], aq, bk[2], bk[3]);
            }
        }
        float cm_lo = -1e30f, cm_hi = -1e30f;
        #pragma unroll
        for (int nt = 0; nt < 8; nt++) {
            int colg = k0 + nt * 8 + (lane & 3) * 2;
            float kn0 = keepneg[colg], kn1 = keepneg[colg + 1];
            S[nt][0] = S[nt][0] * 0.125f + kn0;
            S[nt][1] = S[nt][1] * 0.125f + kn1;
            S[nt][2] = S[nt][2] * 0.125f + kn0;
            S[nt][3] = S[nt][3] * 0.125f + kn1;
            cm_lo = fmaxf(cm_lo, fmaxf(S[nt][0], S[nt][1]));
            cm_hi = fmaxf(cm_hi, fmaxf(S[nt][2], S[nt][3]));
        }
        cm_lo = fmaxf(cm_lo, __shfl_xor_sync(~0u, cm_lo, 1));
        cm_lo = fmaxf(cm_lo, __shfl_xor_sync(~0u, cm_lo, 2));
        cm_hi = fmaxf(cm_hi, __shfl_xor_sync(~0u, cm_hi, 1));
        cm_hi = fmaxf(cm_hi, __shfl_xor_sync(~0u, cm_hi, 2));
        float mn_lo = fmaxf(mr_lo, cm_lo), mn_hi = fmaxf(mr_hi, cm_hi);
        float al_lo = __expf(mr_lo - mn_lo), al_hi = __expf(mr_hi - mn_hi);
        mr_lo = mn_lo; mr_hi = mn_hi;
        sr_lo *= al_lo; sr_hi *= al_hi;
        #pragma unroll
        for (int n = 0; n < 8; n++) {
            O[n][0] *= al_lo; O[n][1] *= al_lo;
            O[n][2] *= al_hi; O[n][3] *= al_hi;
        }
        uint32_t pa[4][4];
        #pragma unroll
        for (int kt = 0; kt < 4; kt++) {
            int t0 = 2 * kt, t1 = 2 * kt + 1;
            float p00 = __expf(S[t0][0] - mn_lo), p01 = __expf(S[t0][1] - mn_lo);
            float p02 = __expf(S[t0][2] - mn_hi), p03 = __expf(S[t0][3] - mn_hi);
            float p10 = __expf(S[t1][0] - mn_lo), p11 = __expf(S[t1][1] - mn_lo);
            float p12 = __expf(S[t1][2] - mn_hi), p13 = __expf(S[t1][3] - mn_hi);
            sr_lo += p00 + p01 + p10 + p11;
            sr_hi += p02 + p03 + p12 + p13;
            pa[kt][0] = packh(p00, p01);
            pa[kt][1] = packh(p02, p03);
            pa[kt][2] = packh(p10, p11);
            pa[kt][3] = packh(p12, p13);
        }
        #pragma unroll
        for (int kt = 0; kt < 4; kt++) {
            #pragma unroll
            for (int ntp = 0; ntp < 4; ntp++) {
                uint32_t vf[4];
                ldsm4t(vf, vbaseS + (uint32_t)(((k0 + kt * 16 + vrow) * ATS + ntp * 16 + vcol) * 2));
                mma_f16(O[2*ntp],   pa[kt], vf[0], vf[1]);
                mma_f16(O[2*ntp+1], pa[kt], vf[2], vf[3]);
            }
        }
    }
    sr_lo += __shfl_xor_sync(~0u, sr_lo, 1);
    sr_lo += __shfl_xor_sync(~0u, sr_lo, 2);
    sr_hi += __shfl_xor_sync(~0u, sr_hi, 1);
    sr_hi += __shfl_xor_sync(~0u, sr_hi, 2);
    float inv_lo = 1.0f / sr_lo, inv_hi = 1.0f / sr_hi;

    int r_lo = j * 128 + m0 + (lane >> 2);
    int r_hi = r_lo + 8;
    size_t b_lo = ((size_t)b * TT + r_lo) * DD + h * HD;
    size_t b_hi = ((size_t)b * TT + r_hi) * DD + h * HD;
    #pragma unroll
    for (int nt = 0; nt < 8; nt++) {
        int col = nt * 8 + (lane & 3) * 2;
        *(uint32_t*)&Og[b_lo + col] = packh(O[nt][0] * inv_lo, O[nt][1] * inv_lo);
        *(uint32_t*)&Og[b_hi + col] = packh(O[nt][2] * inv_hi, O[nt][3] * inv_hi);
    }
}

// ---------------- global (dilated) attention (mma, single 64-key tile) ----------------
__global__ void __launch_bounds__(128, 1) global_attn_kernel(
    const __half* __restrict__ Qg, const __half* __restrict__ Kg,
    const __half* __restrict__ Vg, const int* __restrict__ pm,
    const float* __restrict__ cosp, const float* __restrict__ sinp,
    __half* __restrict__ Og)
{
    int w = blockIdx.x, h = blockIdx.y, b = blockIdx.z;
    extern __shared__ char smc[];
    __half* Qs = (__half*)smc;
    __half* Ks = Qs + 64 * ATS;
    __half* Vs = Ks + 64 * ATS;
    float* keepneg = (float*)(Vs + 64 * ATS);
    int tid = threadIdx.x, lane = tid & 31;

    #pragma unroll 2
    for (int it = 0; it < 8; it++) {
        int idx = tid + it * 128;
        int r = idx >> 4, d = (idx & 15) * 4;
        int p = r * 64 + w;
        size_t base = ((size_t)b * TT + p) * DD + h * HD;
        float4 cs = *(const float4*)&cosp[p * 64 + d];
        float4 sn = *(const float4*)&sinp[p * 64 + d];
        float qv[4], qo[4], kv[4], ko[4];
        unpack4h(*(const uint2*)&Qg[base + d], qv);
        unpack4h(*(const uint2*)&Qg[base + (d ^ 32)], qo);
        unpack4h(*(const uint2*)&Kg[base + d], kv);
        unpack4h(*(const uint2*)&Kg[base + (d ^ 32)], ko);
        float sg = (d < 32) ? -1.0f : 1.0f;
        float4 qr, kr;
        qr.x = qv[0] * cs.x + sg * qo[0] * sn.x;
        qr.y = qv[1] * cs.y + sg * qo[1] * sn.y;
        qr.z = qv[2] * cs.z + sg * qo[2] * sn.z;
        qr.w = qv[3] * cs.w + sg * qo[3] * sn.w;
        kr.x = kv[0] * cs.x + sg * ko[0] * sn.x;
        kr.y = kv[1] * cs.y + sg * ko[1] * sn.y;
        kr.z = kv[2] * cs.z + sg * ko[2] * sn.z;
        kr.w = kv[3] * cs.w + sg * ko[3] * sn.w;
        *(uint2*)&Qs[r * ATS + d] = pack4h(qr);
        *(uint2*)&Ks[r * ATS + d] = pack4h(kr);
        *(uint2*)&Vs[r * ATS + d] = *(const uint2*)&Vg[base + d];
    }
    if (tid < 64) keepneg[tid] = pm[(size_t)b * TT + tid * 64 + w] ? 0.0f : -1e9f;
    __syncthreads();

    int m0 = (tid >> 5) * 16;
    uint32_t qbase = smem_u32(Qs) + (uint32_t)(((m0 + (lane & 15)) * ATS + ((lane >> 4) << 3)) * 2);
    uint32_t kbaseS = smem_u32(Ks);
    uint32_t vbaseS = smem_u32(Vs);
    uint32_t krow = (lane & 7) + ((lane >> 4) & 1) * 8;
    uint32_t kcol = ((lane >> 3) & 1) * 8;
    uint32_t vrow = (lane & 15);
    uint32_t vcol = (lane >> 4) * 8;

    float S[8][4];
    #pragma unroll
    for (int n = 0; n < 8; n++)
        #pragma unroll
        for (int c = 0; c < 4; c++) S[n][c] = 0.0f;
    #pragma unroll
    for (int kt = 0; kt < 4; kt++) {
        uint32_t aq[4];
        ldsm4(aq, qbase + kt * 32);
        #pragma unroll
        for (int ntp = 0; ntp < 4; ntp++) {
            uint32_t bk[4];
            ldsm4(bk, kbaseS + (uint32_t)(((ntp * 16 + krow) * ATS + kt * 16 + kcol) * 2));
            mma_f16(S[2*ntp],   aq, bk[0], bk[1]);
            mma_f16(S[2*ntp+1], aq, bk[2], bk[3]);
        }
    }
    float cm_lo = -1e30f, cm_hi = -1e30f;
    #pragma unroll
    for (int nt = 0; nt < 8; nt++) {
        int colg = nt * 8 + (lane & 3) * 2;
        float kn0 = keepneg[colg], kn1 = keepneg[colg + 1];
        S[nt][0] = S[nt][0] * 0.125f + kn0;
        S[nt][1] = S[nt][1] * 0.125f + kn1;
        S[nt][2] = S[nt][2] * 0.125f + kn0;
        S[nt][3] = S[nt][3] * 0.125f + kn1;
        cm_lo = fmaxf(cm_lo, fmaxf(S[nt][0], S[nt][1]));
        cm_hi = fmaxf(cm_hi, fmaxf(S[nt][2], S[nt][3]));
    }
    cm_lo = fmaxf(cm_lo, __shfl_xor_sync(~0u, cm_lo, 1));
    cm_lo = fmaxf(cm_lo, __shfl_xor_sync(~0u, cm_lo, 2));
    cm_hi = fmaxf(cm_hi, __shfl_xor_sync(~0u, cm_hi, 1));
    cm_hi = fmaxf(cm_hi, __shfl_xor_sync(~0u, cm_hi, 2));

    float sr_lo = 0.0f, sr_hi = 0.0f;
    uint32_t pa[4][4];
    float O[8][4];
    #pragma unroll
    for (int n = 0; n < 8; n++)
        #pragma unroll
        for (int c = 0; c < 4; c++) O[n][c] = 0.0f;
    #pragma unroll
    for (int kt = 0; kt < 4; kt++) {
        int t0 = 2 * kt, t1 = 2 * kt + 1;
        float p00 = __expf(S[t0][0] - cm_lo), p01 = __expf(S[t0][1] - cm_lo);
        float p02 = __expf(S[t0][2] - cm_hi), p03 = __expf(S[t0][3] - cm_hi);
        float p10 = __expf(S[t1][0] - cm_lo), p11 = __expf(S[t1][1] - cm_lo);
        float p12 = __expf(S[t1][2] - cm_hi), p13 = __expf(S[t1][3] - cm_hi);
        sr_lo += p00 + p01 + p10 + p11;
        sr_hi += p02 + p03 + p12 + p13;
        pa[kt][0] = packh(p00, p01);
        pa[kt][1] = packh(p02, p03);
        pa[kt][2] = packh(p10, p11);
        pa[kt][3] = packh(p12, p13);
    }
    #pragma unroll
    for (int kt = 0; kt < 4; kt++) {
        #pragma unroll
        for (int ntp = 0; ntp < 4; ntp++) {
            uint32_t vf[4];
            ldsm4t(vf, vbaseS + (uint32_t)(((kt * 16 + vrow) * ATS + ntp * 16 + vcol) * 2));
            mma_f16(O[2*ntp],   pa[kt], vf[0], vf[1]);
            mma_f16(O[2*ntp+1], pa[kt], vf[2], vf[3]);
        }
    }
    sr_lo += __shfl_xor_sync(~0u, sr_lo, 1);
    sr_lo += __shfl_xor_sync(~0u, sr_lo, 2);
    sr_hi += __shfl_xor_sync(~0u, sr_hi, 1);
    sr_hi += __shfl_xor_sync(~0u, sr_hi, 2);
    float inv_lo = 1.0f / sr_lo, inv_hi = 1.0f / sr_hi;

    int p_lo = (m0 + (lane >> 2)) * 64 + w;
    int p_hi = p_lo + 8 * 64;
    size_t b_lo = ((size_t)b * TT + p_lo) * DD + h * HD;
    size_t b_hi = ((size_t)b * TT + p_hi) * DD + h * HD;
    #pragma unroll
    for (int nt = 0; nt < 8; nt++) {
        int col = nt * 8 + (lane & 3) * 2;
        *(uint32_t*)&Og[b_lo + col] = packh(O[nt][0] * inv_lo, O[nt][1] * inv_lo);
        *(uint32_t*)&Og[b_hi + col] = packh(O[nt][2] * inv_hi, O[nt][3] * inv_hi);
    }
}

// ---------------- host ----------------
extern "C" void kernel_launch(void* const* d_in, const int* in_sizes, int n_in,
                              void* d_out, int out_size)
{
    const float* x    = (const float*)d_in[0];
    const int*   pm   = (const int*)d_in[1];
    const float* cosp = (const float*)d_in[2];
    const float* sinp = (const float*)d_in[3];
    const float* ln1_g = (const float*)d_in[4];
    const float* ln1_b = (const float*)d_in[5];
    const float* ln2_g = (const float*)d_in[6];
    const float* ln2_b = (const float*)d_in[7];
    const float* ln3_g = (const float*)d_in[8];
    const float* ln3_b = (const float*)d_in[9];
    const float* lq_w = (const float*)d_in[10];
    const float* lq_b = (const float*)d_in[11];
    const float* lk_w = (const float*)d_in[12];
    const float* lk_b = (const float*)d_in[13];
    const float* lv_w = (const float*)d_in[14];
    const float* lv_b = (const float*)d_in[15];
    const float* lo_w = (const float*)d_in[16];
    const float* lo_b = (const float*)d_in[17];
    const float* gq_w = (const float*)d_in[18];
    const float* gq_b = (const float*)d_in[19];
    const float* gk_w = (const float*)d_in[20];
    const float* gk_b = (const float*)d_in[21];
    const float* gv_w = (const float*)d_in[22];
    const float* gv_b = (const float*)d_in[23];
    const float* go_w = (const float*)d_in[24];
    const float* go_b = (const float*)d_in[25];
    const float* f1_w = (const float*)d_in[26];
    const float* f1_b = (const float*)d_in[27];
    const float* f2_w = (const float*)d_in[28];
    const float* f2_b = (const float*)d_in[29];
    const float* f3_w = (const float*)d_in[30];
    const float* f3_b = (const float*)d_in[31];
    float* out = (float*)d_out;

    float* pbcat;
    __half *pxh, *pq, *pkp, *pvp, *pxn, *patt, *ph1, *ph2, *pw;
    cudaGetSymbolAddress((void**)&pxh,   g_xh);
    cudaGetSymbolAddress((void**)&pq,    g_q);
    cudaGetSymbolAddress((void**)&pkp,   g_kp);
    cudaGetSymbolAddress((void**)&pvp,   g_vp);
    cudaGetSymbolAddress((void**)&pbcat, g_bcat);
    cudaGetSymbolAddress((void**)&pxn,   g_xn);
    cudaGetSymbolAddress((void**)&patt,  g_att);
    cudaGetSymbolAddress((void**)&ph1,   g_h1);
    cudaGetSymbolAddress((void**)&ph2,   g_h2);
    cudaGetSymbolAddress((void**)&pw,    g_w);

    const int M = BB * TT;

    size_t smLoc = (size_t)(2 * 256 * ATS + 128 * ATS) * 2 + 256 * 4;
    size_t smGlb = (size_t)(3 * 64 * ATS) * 2 + 64 * 4;
    size_t smGemm = 3 * GSTG;
    cudaFuncSetAttribute(local_attn_kernel,  cudaFuncAttributeMaxDynamicSharedMemorySize, (int)smLoc);
    cudaFuncSetAttribute(global_attn_kernel, cudaFuncAttributeMaxDynamicSharedMemorySize, (int)smGlb);
    cudaFuncSetAttribute(gemm_mma_kernel, cudaFuncAttributeMaxDynamicSharedMemorySize, (int)smGemm);

    const int OLQKV=0, OGQKV=786432, OLO=1572864, OGO=1835008,
              OF1=2097152, OF2=2621440, OF3=3670016;

    dim3 gQKV(6, M / 128);
    dim3 g512(2, M / 128);
    dim3 g1k (4, M / 128);

    BPtrs bp;
    bp.p[0]=lq_b; bp.p[1]=lk_b; bp.p[2]=lv_b; bp.p[3]=gq_b; bp.p[4]=gk_b; bp.p[5]=gv_b;
    setup_kernel<<<2048, 256>>>(bp, lk_b, lv_b);
    WPtrs wp;
    wp.p[0]=lq_w; wp.p[1]=lk_w; wp.p[2]=lv_w; wp.p[3]=gq_w; wp.p[4]=gk_w;
    wp.p[5]=gv_w; wp.p[6]=lo_w; wp.p[7]=go_w; wp.p[8]=f1_w; wp.p[9]=f2_w; wp.p[10]=f3_w;
    cvt_w_kernel<<<dim3(1024, 11), 256>>>(wp);

    // fused: pxh = x*mask (fp16); xn = LN(px)*mask
    ln_kernel<<<M, 128>>>(x, ln1_g, ln1_b, pm, pxn, pxh, 1, 1, 0);

    // local QKV fused (q plain fp16, k/v padded fp16)
    gemm_mma_kernel<<<gQKV, 512, smGemm>>>(pxn, pw+OLQKV, pbcat,
                                           0, pq, pkp, pvp, 0, 0, DD, DD, 0, 2, 1);

    local_attn_kernel<<<dim3(NLOC, HH, BB), 256, smLoc>>>(pq, pm, patt);

    // O proj + residual + mask (fp16 in-place on pxh)
    gemm_mma_kernel<<<g512, 512, smGemm>>>(patt, pw+OLO, lo_b,
                                           0, pxh, 0, 0, pxh, pm, DD, DD, 0, 4, 0);

    ln_kernel<<<M, 128>>>(pxh, ln2_g, ln2_b, pm, pxn, 0, 0, 0, 1);

    // global QKV fused (plain fp16)
    gemm_mma_kernel<<<gQKV, 512, smGemm>>>(pxn, pw+OGQKV, pbcat + 1536,
                                           0, pq, pkp, pvp, 0, 0, DD, DD, 0, 2, 0);

    global_attn_kernel<<<dim3(NDIL, HH, BB), 128, smGlb>>>(pq, pkp, pvp, pm, cosp, sinp, patt);

    gemm_mma_kernel<<<g512, 512, smGemm>>>(patt, pw+OGO, go_b,
                                           0, pxh, 0, 0, pxh, pm, DD, DD, 0, 4, 0);

    ln_kernel<<<M, 128>>>(pxh, ln3_g, ln3_b, pm, pxn, 0, 0, 0, 1);
    gemm_mma_kernel<<<g1k,  512, smGemm>>>(pxn, pw+OF1, f1_b,
                                           0, ph1, 0, 0, 0, 0, 512,  1024, 1, 1, 0);
    gemm_mma_kernel<<<g1k,  512, smGemm>>>(ph1, pw+OF2, f2_b,
                                           0, ph2, 0, 0, 0, 0, 1024, 1024, 1, 1, 0);
    // f3 + fp16 residual + mask -> fp32 out
    gemm_mma_kernel<<<g512, 512, smGemm>>>(ph2, pw+OF3, f3_b,
                                           out, 0, 0, 0, pxh, pm, 1024, 512, 0, 3, 0);
}